// round 4
// baseline (speedup 1.0000x reference)
#include <cuda_runtime.h>
#include <math.h>
#include <stdint.h>

// Problem constants (fixed by the reference)
#define NN   50000      // nodes
#define FF   64         // node features
#define HH   128        // hidden
#define CLSN 64         // classes
#define EE   800000     // edges
#define ELE  200000     // label edges
#define MPAD 50048      // 391 * 128, padded M (no row guards on scratch)
#define KCAT 192        // FF + HH
#define NG   512        // 4*HH

// ---------------- scratch (device globals: allocation-free, zero-initialized) ----
__device__ float g_deg  [MPAD];
__device__ float g_dinv [MPAD];
__device__ int   g_off  [MPAD];                 // CSR row offsets (by dst)
__device__ int   g_cur  [MPAD];                 // fill cursors
__device__ int   g_esrc [EE];                   // CSR: src per slot
__device__ float g_xw   [(size_t)MPAD * FF];    // x @ W_gcn
__device__ float g_abuf [(size_t)MPAD * KCAT];  // [h | hidden1], tf32-rounded
__device__ float g_B2   [KCAT * NG];            // [Wx ; Th], gate-interleaved cols, tf32
__device__ float g_bias2[NG];                   // b_gate + b_conv, gate-interleaved
__device__ float g_hn   [(size_t)MPAD * HH];    // relu(H_new)
__device__ float g_z    [(size_t)MPAD * CLSN];  // softmax output

__device__ __forceinline__ float sigm(float x) { return 1.0f / (1.0f + expf(-x)); }

__device__ __forceinline__ float to_tf32(float x) {
    uint32_t o;
    asm("cvt.rna.tf32.f32 %0, %1;" : "=r"(o) : "f"(x));
    return __uint_as_float(o);
}

// ---------------- init: deg = 1 (self loop) -------------------------------------
__global__ void init_kernel() {
    int i = blockIdx.x * blockDim.x + threadIdx.x;
    if (i < NN) g_deg[i] = 1.0f;
}

__global__ void deg_kernel(const int* __restrict__ dst) {
    int e = blockIdx.x * blockDim.x + threadIdx.x;
    if (e < EE) atomicAdd(&g_deg[dst[e]], 1.0f);
}

__global__ void dinv_kernel() {
    int i = blockIdx.x * blockDim.x + threadIdx.x;
    if (i < NN) g_dinv[i] = rsqrtf(g_deg[i]);
}

// ---------------- exclusive scan of edge counts (one CTA) -----------------------
#define SCAN_T 1024
#define SCAN_CHUNK 49           // 1024*49 = 50176 >= NN

__global__ void __launch_bounds__(SCAN_T)
scan_kernel() {
    __shared__ int ssum[SCAN_T];
    int t = threadIdx.x;
    int beg = t * SCAN_CHUNK;
    int end = min(beg + SCAN_CHUNK, NN);
    int s = 0;
    for (int i = beg; i < end; i++) s += (int)g_deg[i] - 1;
    ssum[t] = s;
    __syncthreads();
    #pragma unroll
    for (int off = 1; off < SCAN_T; off <<= 1) {
        int v = (t >= off) ? ssum[t - off] : 0;
        __syncthreads();
        ssum[t] += v;
        __syncthreads();
    }
    int run = ssum[t] - s;      // exclusive prefix
    for (int i = beg; i < end; i++) {
        g_off[i] = run;
        g_cur[i] = run;
        run += (int)g_deg[i] - 1;
    }
}

// ---------------- CSR fill: slot per (dst) edge, store src ----------------------
__global__ void fill_kernel(const int* __restrict__ src, const int* __restrict__ dst) {
    int e = blockIdx.x * blockDim.x + threadIdx.x;
    if (e >= EE) return;
    int slot = atomicAdd(&g_cur[dst[e]], 1);
    g_esrc[slot] = src[e];
}

// ---------------- fp32 GEMM1: g_xw = x @ W_gcn (M=NN guarded, K=N=64) ----------
#define BM 64
#define BK 16

__global__ void __launch_bounds__(256)
sgemm1(const float* __restrict__ A, const float* __restrict__ B)
{
    __shared__ float As[BK][BM];
    __shared__ float Bs[BK][64];

    const int tid = threadIdx.x;
    const int tx = tid & 15, ty = tid >> 4;
    const int rowBase = blockIdx.y * BM;

    const int ar = tid >> 2;
    const int ac = (tid & 3) * 4;
    const int br = tid >> 4;
    const int bc = (tid & 15) * 4;

    float acc[4][4] = {};

    for (int k0 = 0; k0 < FF; k0 += BK) {
        float4 av = make_float4(0.f, 0.f, 0.f, 0.f);
        int arow = rowBase + ar;
        if (arow < NN)
            av = *reinterpret_cast<const float4*>(&A[(size_t)arow * FF + k0 + ac]);
        As[ac + 0][ar] = av.x; As[ac + 1][ar] = av.y;
        As[ac + 2][ar] = av.z; As[ac + 3][ar] = av.w;

        float4 bv = *reinterpret_cast<const float4*>(&B[(size_t)(k0 + br) * FF + bc]);
        *reinterpret_cast<float4*>(&Bs[br][bc]) = bv;
        __syncthreads();

        #pragma unroll
        for (int kk = 0; kk < BK; kk++) {
            float4 a4 = *reinterpret_cast<const float4*>(&As[kk][ty * 4]);
            float4 b4 = *reinterpret_cast<const float4*>(&Bs[kk][tx * 4]);
            float ra[4] = {a4.x, a4.y, a4.z, a4.w};
            float rb[4] = {b4.x, b4.y, b4.z, b4.w};
            #pragma unroll
            for (int i = 0; i < 4; i++)
                #pragma unroll
                for (int j = 0; j < 4; j++)
                    acc[i][j] += ra[i] * rb[j];
        }
        __syncthreads();
    }

    #pragma unroll
    for (int i = 0; i < 4; i++) {
        size_t row = rowBase + ty * 4 + i;      // padded g_xw: no store guard
        float* crow = &g_xw[row * FF + tx * 4];
        #pragma unroll
        for (int j = 0; j < 4; j++) crow[j] = acc[i][j];
    }
}

// ---------------- gather + build abuf: fused GCN agg + [h|h1] pack --------------
// 16 lanes per node; agg = dinv[d]*(sum dinv[s]*xw[s]) + dinv[d]^2*xw[d] + bgcn
__global__ void __launch_bounds__(256)
gather_kernel(const float* __restrict__ bgcn, const float* __restrict__ h1)
{
    int t = blockIdx.x * blockDim.x + threadIdx.x;
    int n = t >> 4, lane = t & 15;
    if (n >= NN) return;

    const float4* xw4 = reinterpret_cast<const float4*>(g_xw);
    int beg = g_off[n];
    int cnt = (int)g_deg[n] - 1;

    float4 acc = make_float4(0.f, 0.f, 0.f, 0.f);
    for (int i = beg; i < beg + cnt; i++) {
        int s = __ldg(&g_esrc[i]);
        float w = __ldg(&g_dinv[s]);
        float4 v = __ldg(&xw4[(size_t)s * 16 + lane]);
        acc.x += w * v.x; acc.y += w * v.y; acc.z += w * v.z; acc.w += w * v.w;
    }
    float dn = g_dinv[n];
    float4 self = xw4[(size_t)n * 16 + lane];
    float4 bg = *reinterpret_cast<const float4*>(&bgcn[lane * 4]);
    float4 h;
    h.x = to_tf32(dn * acc.x + dn * dn * self.x + bg.x);
    h.y = to_tf32(dn * acc.y + dn * dn * self.y + bg.y);
    h.z = to_tf32(dn * acc.z + dn * dn * self.z + bg.z);
    h.w = to_tf32(dn * acc.w + dn * dn * self.w + bg.w);
    *reinterpret_cast<float4*>(&g_abuf[(size_t)n * KCAT + lane * 4]) = h;

    // h1 part: 128 floats per node, 8 per lane (2 float4)
    const float4* h14 = reinterpret_cast<const float4*>(h1);
    #pragma unroll
    for (int q = 0; q < 2; q++) {
        float4 v = __ldg(&h14[(size_t)n * 32 + lane * 2 + q]);
        v.x = to_tf32(v.x); v.y = to_tf32(v.y); v.z = to_tf32(v.z); v.w = to_tf32(v.w);
        *reinterpret_cast<float4*>(&g_abuf[(size_t)n * KCAT + FF + lane * 8 + q * 4]) = v;
    }
}

// ---------------- pack B2: gate-interleaved columns, tf32-rounded ----------------
__global__ void pack_B2(const float* __restrict__ Wx, const float* __restrict__ Th,
                        const float* __restrict__ bgate, const float* __restrict__ bconv)
{
    int i = blockIdx.x * blockDim.x + threadIdx.x;
    if (i >= KCAT * NG) return;
    int k = i / NG, col = i - k * NG;
    int j = col >> 2, g = col & 3;
    int old = g * HH + j;
    float v = (k < FF) ? Wx[(size_t)k * NG + old] : Th[(size_t)(k - FF) * NG + old];
    g_B2[i] = to_tf32(v);
    if (i < NG) g_bias2[i] = bgate[old] + bconv[old];
}

// ---------------- tf32 MMA GEMM2 + fused LSTM gate epilogue ---------------------
#define AS_STRIDE 36
#define BS_STRIDE 72
#define CS_STRIDE 68

__device__ __forceinline__ void mma8(float* c, const uint32_t* a, const uint32_t* b) {
    asm volatile("mma.sync.aligned.m16n8k8.row.col.f32.tf32.tf32.f32 "
        "{%0,%1,%2,%3}, {%4,%5,%6,%7}, {%8,%9}, {%0,%1,%2,%3};"
        : "+f"(c[0]), "+f"(c[1]), "+f"(c[2]), "+f"(c[3])
        : "r"(a[0]), "r"(a[1]), "r"(a[2]), "r"(a[3]), "r"(b[0]), "r"(b[1]));
}

__global__ void __launch_bounds__(256)
gemm2_gates(const float* __restrict__ h2, const float* __restrict__ wc,
            float* __restrict__ outC)
{
    __shared__ __align__(16) float sm[8704];
    float* As = sm;                                // [128][36]
    float* Bs = sm + 128 * AS_STRIDE;              // [32][72]
    float* Cs = sm;                                // [128][68] after mma

    const int tid  = threadIdx.x;
    const int lane = tid & 31, warp = tid >> 5;
    const int wm = warp & 3, wn = warp >> 2;
    const int gid = lane >> 2, tg = lane & 3;
    const int rowBase = blockIdx.y * 128;
    const int colBase = blockIdx.x * 64;

    // register prefetch addressing
    const int am = tid >> 3, ak4 = (tid & 7) << 2;           // A: row, k-offset
    const int bk = tid >> 4, bn4 = (tid & 15) << 2;          // B: k, n-offset
    const float* aptr = &g_abuf[(size_t)(rowBase + am) * KCAT + ak4];
    const float* bptr = &g_B2[(size_t)bk * NG + colBase + bn4];

    float acc[2][4][4];
    #pragma unroll
    for (int mt = 0; mt < 2; mt++)
        #pragma unroll
        for (int nt = 0; nt < 4; nt++)
            #pragma unroll
            for (int r = 0; r < 4; r++) acc[mt][nt][r] = 0.0f;

    float4 ra[4], rb[2];
    #pragma unroll
    for (int it = 0; it < 4; it++)
        ra[it] = *reinterpret_cast<const float4*>(aptr + (size_t)(it * 32) * KCAT);
    #pragma unroll
    for (int it = 0; it < 2; it++)
        rb[it] = *reinterpret_cast<const float4*>(bptr + (size_t)(it * 16) * NG);

    #pragma unroll
    for (int c = 0; c < 6; c++) {
        __syncthreads();
        #pragma unroll
        for (int it = 0; it < 4; it++)
            *reinterpret_cast<float4*>(&As[(am + it * 32) * AS_STRIDE + ak4]) = ra[it];
        #pragma unroll
        for (int it = 0; it < 2; it++)
            *reinterpret_cast<float4*>(&Bs[(bk + it * 16) * BS_STRIDE + bn4]) = rb[it];
        __syncthreads();

        if (c < 5) {
            int kc = (c + 1) * 32;
            #pragma unroll
            for (int it = 0; it < 4; it++)
                ra[it] = *reinterpret_cast<const float4*>(aptr + (size_t)(it * 32) * KCAT + kc);
            #pragma unroll
            for (int it = 0; it < 2; it++)
                rb[it] = *reinterpret_cast<const float4*>(bptr + (size_t)(it * 16 + kc) * NG);
        }

        #pragma unroll
        for (int ks = 0; ks < 32; ks += 8) {
            uint32_t a[2][4], b[4][2];
            #pragma unroll
            for (int mt = 0; mt < 2; mt++) {
                int r0 = wm * 32 + mt * 16 + gid;
                a[mt][0] = __float_as_uint(As[r0 * AS_STRIDE + ks + tg]);
                a[mt][1] = __float_as_uint(As[(r0 + 8) * AS_STRIDE + ks + tg]);
                a[mt][2] = __float_as_uint(As[r0 * AS_STRIDE + ks + tg + 4]);
                a[mt][3] = __float_as_uint(As[(r0 + 8) * AS_STRIDE + ks + tg + 4]);
            }
            #pragma unroll
            for (int nt = 0; nt < 4; nt++) {
                int c0 = wn * 32 + nt * 8 + gid;
                b[nt][0] = __float_as_uint(Bs[(ks + tg) * BS_STRIDE + c0]);
                b[nt][1] = __float_as_uint(Bs[(ks + tg + 4) * BS_STRIDE + c0]);
            }
            #pragma unroll
            for (int mt = 0; mt < 2; mt++)
                #pragma unroll
                for (int nt = 0; nt < 4; nt++)
                    mma8(acc[mt][nt], a[mt], b[nt]);
        }
    }

    __syncthreads();
    #pragma unroll
    for (int mt = 0; mt < 2; mt++)
        #pragma unroll
        for (int nt = 0; nt < 4; nt++) {
            int r = wm * 32 + mt * 16 + gid;
            int c = wn * 32 + nt * 8 + tg * 2;
            *reinterpret_cast<float2*>(&Cs[r * CS_STRIDE + c]) =
                make_float2(acc[mt][nt][0], acc[mt][nt][1]);
            *reinterpret_cast<float2*>(&Cs[(r + 8) * CS_STRIDE + c]) =
                make_float2(acc[mt][nt][2], acc[mt][nt][3]);
        }
    __syncthreads();

    const int j16 = tid & 15;
    const int rl0 = tid >> 4;
    const int jg = (colBase >> 2) + j16;
    const float w0 = wc[jg], w1 = wc[HH + jg], w2 = wc[2 * HH + jg];
    const float4 bias = *reinterpret_cast<const float4*>(&g_bias2[colBase + j16 * 4]);

    #pragma unroll
    for (int p = 0; p < 8; p++) {
        int rl = p * 16 + rl0;
        int row = rowBase + rl;
        if (row < NN) {
            float4 v = *reinterpret_cast<const float4*>(&Cs[rl * CS_STRIDE + j16 * 4]);
            float c2 = h2[(size_t)row * HH + jg];
            float I  = sigm(v.x + bias.x + w0 * c2);
            float Fg = sigm(v.y + bias.y + w1 * c2);
            float Cn = Fg * c2 + I * tanhf(v.z + bias.z);
            float O  = sigm(v.w + bias.w + w2 * Cn);
            outC[(size_t)row * HH + jg] = Cn;
            g_hn[(size_t)row * HH + jg] = fmaxf(O * tanhf(Cn), 0.0f);
        }
    }
}

// ---------------- Linear + softmax ----------------------------------------------
__global__ void __launch_bounds__(256)
lin_softmax(const float* __restrict__ Wl, const float* __restrict__ bl)
{
    __shared__ float sW[HH * CLSN];
    __shared__ float sb[CLSN];
    __shared__ float sh[8][HH];

    int tid = threadIdx.x;
    for (int i = tid * 4; i < HH * CLSN; i += 256 * 4)
        *reinterpret_cast<float4*>(&sW[i]) = *reinterpret_cast<const float4*>(&Wl[i]);
    if (tid < CLSN) sb[tid] = bl[tid];
    int warp = tid >> 5, lane = tid & 31;
    int n = blockIdx.x * 8 + warp;
    __syncthreads();

    if (n < NN) {
        for (int k = lane; k < HH; k += 32) sh[warp][k] = g_hn[(size_t)n * HH + k];
        __syncwarp();
        float a0 = sb[lane], a1 = sb[lane + 32];
        #pragma unroll 8
        for (int k = 0; k < HH; k++) {
            float hv = sh[warp][k];
            a0 += hv * sW[k * CLSN + lane];
            a1 += hv * sW[k * CLSN + lane + 32];
        }
        float m = fmaxf(a0, a1);
        #pragma unroll
        for (int o = 16; o; o >>= 1) m = fmaxf(m, __shfl_xor_sync(0xFFFFFFFFu, m, o));
        float e0 = expf(a0 - m), e1 = expf(a1 - m);
        float s = e0 + e1;
        #pragma unroll
        for (int o = 16; o; o >>= 1) s += __shfl_xor_sync(0xFFFFFFFFu, s, o);
        float inv = 1.0f / s;
        g_z[(size_t)n * CLSN + lane]      = e0 * inv;
        g_z[(size_t)n * CLSN + lane + 32] = e1 * inv;
    }
}

// ---------------- decode --------------------------------------------------------
__global__ void decode_kernel(const int* __restrict__ s, const int* __restrict__ d,
                              float* __restrict__ r)
{
    int w = (blockIdx.x * blockDim.x + threadIdx.x) >> 5;
    int lane = threadIdx.x & 31;
    if (w >= ELE) return;
    int a = __ldg(&s[w]);
    int b = __ldg(&d[w]);
    float acc = g_z[(size_t)a * CLSN + lane]      * g_z[(size_t)b * CLSN + lane]
              + g_z[(size_t)a * CLSN + lane + 32] * g_z[(size_t)b * CLSN + lane + 32];
    #pragma unroll
    for (int o = 16; o; o >>= 1) acc += __shfl_xor_sync(0xFFFFFFFFu, acc, o);
    if (lane == 0) r[w] = acc;
}

// ---------------- copy hidden1 passthrough --------------------------------------
__global__ void copy_h1(const float* __restrict__ h1, float* __restrict__ out) {
    int i = blockIdx.x * blockDim.x + threadIdx.x;
    if (i < NN * HH / 4)
        reinterpret_cast<float4*>(out)[i] = reinterpret_cast<const float4*>(h1)[i];
}

// ================================================================================
extern "C" void kernel_launch(void* const* d_in, const int* in_sizes, int n_in,
                              void* d_out, int out_size)
{
    const float* x    = (const float*)d_in[0];
    const int*   ei   = (const int*)d_in[1];
    const int*   eli  = (const int*)d_in[2];
    const float* h1   = (const float*)d_in[3];
    const float* h2   = (const float*)d_in[4];
    const float* Wgcn = (const float*)d_in[5];
    const float* bgcn = (const float*)d_in[6];
    const float* Wx   = (const float*)d_in[7];
    const float* Th   = (const float*)d_in[8];
    const float* bgate= (const float*)d_in[9];
    const float* bconv= (const float*)d_in[10];
    const float* wc   = (const float*)d_in[11];
    const float* Wlin = (const float*)d_in[12];
    const float* blin = (const float*)d_in[13];

    float* out   = (float*)d_out;
    float* out_r = out;
    float* out_h = out + ELE;
    float* out_c = out + ELE + (size_t)NN * HH;

    const int T = 256;

    init_kernel<<<(NN + T - 1) / T, T>>>();
    deg_kernel<<<(EE + T - 1) / T, T>>>(ei + EE);
    dinv_kernel<<<(NN + T - 1) / T, T>>>();
    scan_kernel<<<1, SCAN_T>>>();
    fill_kernel<<<(EE + T - 1) / T, T>>>(ei, ei + EE);
    {
        dim3 grid(1, MPAD / BM);
        sgemm1<<<grid, 256>>>(x, Wgcn);
    }
    pack_B2<<<(KCAT * NG + T - 1) / T, T>>>(Wx, Th, bgate, bconv);
    gather_kernel<<<(NN * 16 + T - 1) / T, T>>>(bgcn, h1);
    {
        dim3 grid(NG / 64, MPAD / 128);
        gemm2_gates<<<grid, 256>>>(h2, wc, out_c);
    }
    lin_softmax<<<(NN + 7) / 8, 256>>>(Wlin, blin);
    decode_kernel<<<(ELE * 32 + T - 1) / T, T>>>(eli, eli + ELE, out_r);
    copy_h1<<<(NN * HH / 4 + T - 1) / T, T>>>(h1, out_h);
}

// round 5
// speedup vs baseline: 1.2134x; 1.2134x over previous
#include <cuda_runtime.h>
#include <math.h>
#include <stdint.h>

// Problem constants (fixed by the reference)
#define NN   50000      // nodes
#define FF   64         // node features
#define HH   128        // hidden
#define CLSN 64         // classes
#define EE   800000     // edges
#define ELE  200000     // label edges
#define MPAD 50048      // 391 * 128, padded M (no row guards on scratch)
#define KCAT 192        // FF + HH
#define NG   512        // 4*HH

#define SCAN_B 49       // ceil(NN / 1024)

// ---------------- scratch (device globals: allocation-free, zero-initialized) ----
__device__ float g_deg  [MPAD];
__device__ float g_dinv [MPAD];
__device__ int   g_off  [MPAD];                 // CSR row offsets (by dst)
__device__ int   g_cur  [MPAD];                 // fill cursors
__device__ int   g_bsum [64];                   // per-block totals
__device__ int   g_bbase[64];                   // exclusive block bases
__device__ int   g_esrc [EE];                   // CSR: src per slot
__device__ float g_xw   [(size_t)MPAD * FF];    // x @ W_gcn
__device__ float g_abuf [(size_t)MPAD * KCAT];  // [h | hidden1], tf32-rounded
__device__ float g_B2   [KCAT * NG];            // [Wx ; Th], gate-interleaved cols, tf32
__device__ float g_bias2[NG];                   // b_gate + b_conv, gate-interleaved
__device__ float g_hn   [(size_t)MPAD * HH];    // relu(H_new)
__device__ float g_z    [(size_t)MPAD * CLSN];  // softmax output

__device__ __forceinline__ float sigm(float x) { return 1.0f / (1.0f + expf(-x)); }

__device__ __forceinline__ float to_tf32(float x) {
    uint32_t o;
    asm("cvt.rna.tf32.f32 %0, %1;" : "=r"(o) : "f"(x));
    return __uint_as_float(o);
}

// ---------------- init: deg = 1 (self loop) -------------------------------------
__global__ void init_kernel() {
    int i = blockIdx.x * blockDim.x + threadIdx.x;
    if (i < NN) g_deg[i] = 1.0f;
}

__global__ void deg_kernel(const int* __restrict__ dst) {
    int e = blockIdx.x * blockDim.x + threadIdx.x;
    if (e < EE) atomicAdd(&g_deg[dst[e]], 1.0f);
}

__global__ void dinv_kernel() {
    int i = blockIdx.x * blockDim.x + threadIdx.x;
    if (i < NN) g_dinv[i] = rsqrtf(g_deg[i]);
}

// ---------------- parallel 3-pass exclusive scan of edge counts -----------------
// pass 1: per-block exclusive scan (warp shuffle + cross-warp), block totals
__global__ void __launch_bounds__(1024)
scan_blocks() {
    __shared__ int wsum[32];
    int t = threadIdx.x, i = blockIdx.x * 1024 + t;
    int lane = t & 31, warp = t >> 5;
    int cnt = (i < NN) ? ((int)g_deg[i] - 1) : 0;

    int inc = cnt;
    #pragma unroll
    for (int o = 1; o < 32; o <<= 1) {
        int v = __shfl_up_sync(0xFFFFFFFFu, inc, o);
        if (lane >= o) inc += v;
    }
    if (lane == 31) wsum[warp] = inc;
    __syncthreads();
    if (warp == 0) {
        int w = wsum[lane];
        #pragma unroll
        for (int o = 1; o < 32; o <<= 1) {
            int v = __shfl_up_sync(0xFFFFFFFFu, w, o);
            if (lane >= o) w += v;
        }
        wsum[lane] = w;
        if (lane == 31) g_bsum[blockIdx.x] = w;   // block total
    }
    __syncthreads();
    int base = (warp > 0) ? wsum[warp - 1] : 0;
    if (i < NN) g_off[i] = base + inc - cnt;      // block-local exclusive prefix
}

// pass 2: scan 49 block totals (one tiny CTA)
__global__ void __launch_bounds__(64)
scan_bases() {
    __shared__ int s[64];
    int t = threadIdx.x;
    s[t] = (t < SCAN_B) ? g_bsum[t] : 0;
    __syncthreads();
    #pragma unroll
    for (int o = 1; o < 64; o <<= 1) {
        int v = (t >= o) ? s[t - o] : 0;
        __syncthreads();
        s[t] += v;
        __syncthreads();
    }
    if (t < SCAN_B) g_bbase[t] = s[t] - g_bsum[t];  // exclusive
}

// pass 3: add block base, init cursors
__global__ void __launch_bounds__(1024)
scan_fixup() {
    int i = blockIdx.x * 1024 + threadIdx.x;
    if (i < NN) {
        int o = g_off[i] + g_bbase[blockIdx.x];
        g_off[i] = o;
        g_cur[i] = o;
    }
}

// ---------------- CSR fill: slot per (dst) edge, store src ----------------------
__global__ void fill_kernel(const int* __restrict__ src, const int* __restrict__ dst) {
    int e = blockIdx.x * blockDim.x + threadIdx.x;
    if (e >= EE) return;
    int slot = atomicAdd(&g_cur[dst[e]], 1);
    g_esrc[slot] = src[e];
}

// ---------------- fp32 GEMM1: g_xw = x @ W_gcn (M=NN guarded, K=N=64) ----------
#define BM 64
#define BK 16

__global__ void __launch_bounds__(256)
sgemm1(const float* __restrict__ A, const float* __restrict__ B)
{
    __shared__ float As[BK][BM];
    __shared__ float Bs[BK][64];

    const int tid = threadIdx.x;
    const int tx = tid & 15, ty = tid >> 4;
    const int rowBase = blockIdx.y * BM;

    const int ar = tid >> 2;
    const int ac = (tid & 3) * 4;
    const int br = tid >> 4;
    const int bc = (tid & 15) * 4;

    float acc[4][4] = {};

    for (int k0 = 0; k0 < FF; k0 += BK) {
        float4 av = make_float4(0.f, 0.f, 0.f, 0.f);
        int arow = rowBase + ar;
        if (arow < NN)
            av = *reinterpret_cast<const float4*>(&A[(size_t)arow * FF + k0 + ac]);
        As[ac + 0][ar] = av.x; As[ac + 1][ar] = av.y;
        As[ac + 2][ar] = av.z; As[ac + 3][ar] = av.w;

        float4 bv = *reinterpret_cast<const float4*>(&B[(size_t)(k0 + br) * FF + bc]);
        *reinterpret_cast<float4*>(&Bs[br][bc]) = bv;
        __syncthreads();

        #pragma unroll
        for (int kk = 0; kk < BK; kk++) {
            float4 a4 = *reinterpret_cast<const float4*>(&As[kk][ty * 4]);
            float4 b4 = *reinterpret_cast<const float4*>(&Bs[kk][tx * 4]);
            float ra[4] = {a4.x, a4.y, a4.z, a4.w};
            float rb[4] = {b4.x, b4.y, b4.z, b4.w};
            #pragma unroll
            for (int i = 0; i < 4; i++)
                #pragma unroll
                for (int j = 0; j < 4; j++)
                    acc[i][j] += ra[i] * rb[j];
        }
        __syncthreads();
    }

    #pragma unroll
    for (int i = 0; i < 4; i++) {
        size_t row = rowBase + ty * 4 + i;      // padded g_xw: no store guard
        float* crow = &g_xw[row * FF + tx * 4];
        #pragma unroll
        for (int j = 0; j < 4; j++) crow[j] = acc[i][j];
    }
}

// ---------------- gather + build abuf: fused GCN agg + [h|h1] pack --------------
__global__ void __launch_bounds__(256)
gather_kernel(const float* __restrict__ bgcn, const float* __restrict__ h1)
{
    int t = blockIdx.x * blockDim.x + threadIdx.x;
    int n = t >> 4, lane = t & 15;
    if (n >= NN) return;

    const float4* xw4 = reinterpret_cast<const float4*>(g_xw);
    int beg = g_off[n];
    int cnt = (int)g_deg[n] - 1;

    float4 acc = make_float4(0.f, 0.f, 0.f, 0.f);
    for (int i = beg; i < beg + cnt; i++) {
        int s = __ldg(&g_esrc[i]);
        float w = __ldg(&g_dinv[s]);
        float4 v = __ldg(&xw4[(size_t)s * 16 + lane]);
        acc.x += w * v.x; acc.y += w * v.y; acc.z += w * v.z; acc.w += w * v.w;
    }
    float dn = g_dinv[n];
    float4 self = xw4[(size_t)n * 16 + lane];
    float4 bg = *reinterpret_cast<const float4*>(&bgcn[lane * 4]);
    float4 h;
    h.x = to_tf32(dn * acc.x + dn * dn * self.x + bg.x);
    h.y = to_tf32(dn * acc.y + dn * dn * self.y + bg.y);
    h.z = to_tf32(dn * acc.z + dn * dn * self.z + bg.z);
    h.w = to_tf32(dn * acc.w + dn * dn * self.w + bg.w);
    *reinterpret_cast<float4*>(&g_abuf[(size_t)n * KCAT + lane * 4]) = h;

    const float4* h14 = reinterpret_cast<const float4*>(h1);
    #pragma unroll
    for (int q = 0; q < 2; q++) {
        float4 v = __ldg(&h14[(size_t)n * 32 + lane * 2 + q]);
        v.x = to_tf32(v.x); v.y = to_tf32(v.y); v.z = to_tf32(v.z); v.w = to_tf32(v.w);
        *reinterpret_cast<float4*>(&g_abuf[(size_t)n * KCAT + FF + lane * 8 + q * 4]) = v;
    }
}

// ---------------- pack B2: gate-interleaved columns, tf32-rounded ----------------
__global__ void pack_B2(const float* __restrict__ Wx, const float* __restrict__ Th,
                        const float* __restrict__ bgate, const float* __restrict__ bconv)
{
    int i = blockIdx.x * blockDim.x + threadIdx.x;
    if (i >= KCAT * NG) return;
    int k = i / NG, col = i - k * NG;
    int j = col >> 2, g = col & 3;
    int old = g * HH + j;
    float v = (k < FF) ? Wx[(size_t)k * NG + old] : Th[(size_t)(k - FF) * NG + old];
    g_B2[i] = to_tf32(v);
    if (i < NG) g_bias2[i] = bgate[old] + bconv[old];
}

// ---------------- tf32 MMA GEMM2 + fused LSTM gate epilogue ---------------------
#define AS_STRIDE 36
#define BS_STRIDE 72
#define CS_STRIDE 68

__device__ __forceinline__ void mma8(float* c, const uint32_t* a, const uint32_t* b) {
    asm volatile("mma.sync.aligned.m16n8k8.row.col.f32.tf32.tf32.f32 "
        "{%0,%1,%2,%3}, {%4,%5,%6,%7}, {%8,%9}, {%0,%1,%2,%3};"
        : "+f"(c[0]), "+f"(c[1]), "+f"(c[2]), "+f"(c[3])
        : "r"(a[0]), "r"(a[1]), "r"(a[2]), "r"(a[3]), "r"(b[0]), "r"(b[1]));
}

__global__ void __launch_bounds__(256)
gemm2_gates(const float* __restrict__ h2, const float* __restrict__ wc,
            float* __restrict__ outC)
{
    __shared__ __align__(16) float sm[8704];
    float* As = sm;                                // [128][36]
    float* Bs = sm + 128 * AS_STRIDE;              // [32][72]
    float* Cs = sm;                                // [128][68] after mma

    const int tid  = threadIdx.x;
    const int lane = tid & 31, warp = tid >> 5;
    const int wm = warp & 3, wn = warp >> 2;
    const int gid = lane >> 2, tg = lane & 3;
    const int rowBase = blockIdx.y * 128;
    const int colBase = blockIdx.x * 64;

    const int am = tid >> 3, ak4 = (tid & 7) << 2;
    const int bk = tid >> 4, bn4 = (tid & 15) << 2;
    const float* aptr = &g_abuf[(size_t)(rowBase + am) * KCAT + ak4];
    const float* bptr = &g_B2[(size_t)bk * NG + colBase + bn4];

    float acc[2][4][4];
    #pragma unroll
    for (int mt = 0; mt < 2; mt++)
        #pragma unroll
        for (int nt = 0; nt < 4; nt++)
            #pragma unroll
            for (int r = 0; r < 4; r++) acc[mt][nt][r] = 0.0f;

    float4 ra[4], rb[2];
    #pragma unroll
    for (int it = 0; it < 4; it++)
        ra[it] = *reinterpret_cast<const float4*>(aptr + (size_t)(it * 32) * KCAT);
    #pragma unroll
    for (int it = 0; it < 2; it++)
        rb[it] = *reinterpret_cast<const float4*>(bptr + (size_t)(it * 16) * NG);

    #pragma unroll
    for (int c = 0; c < 6; c++) {
        __syncthreads();
        #pragma unroll
        for (int it = 0; it < 4; it++)
            *reinterpret_cast<float4*>(&As[(am + it * 32) * AS_STRIDE + ak4]) = ra[it];
        #pragma unroll
        for (int it = 0; it < 2; it++)
            *reinterpret_cast<float4*>(&Bs[(bk + it * 16) * BS_STRIDE + bn4]) = rb[it];
        __syncthreads();

        if (c < 5) {
            int kc = (c + 1) * 32;
            #pragma unroll
            for (int it = 0; it < 4; it++)
                ra[it] = *reinterpret_cast<const float4*>(aptr + (size_t)(it * 32) * KCAT + kc);
            #pragma unroll
            for (int it = 0; it < 2; it++)
                rb[it] = *reinterpret_cast<const float4*>(bptr + (size_t)(it * 16 + kc) * NG);
        }

        #pragma unroll
        for (int ks = 0; ks < 32; ks += 8) {
            uint32_t a[2][4], b[4][2];
            #pragma unroll
            for (int mt = 0; mt < 2; mt++) {
                int r0 = wm * 32 + mt * 16 + gid;
                a[mt][0] = __float_as_uint(As[r0 * AS_STRIDE + ks + tg]);
                a[mt][1] = __float_as_uint(As[(r0 + 8) * AS_STRIDE + ks + tg]);
                a[mt][2] = __float_as_uint(As[r0 * AS_STRIDE + ks + tg + 4]);
                a[mt][3] = __float_as_uint(As[(r0 + 8) * AS_STRIDE + ks + tg + 4]);
            }
            #pragma unroll
            for (int nt = 0; nt < 4; nt++) {
                int c0 = wn * 32 + nt * 8 + gid;
                b[nt][0] = __float_as_uint(Bs[(ks + tg) * BS_STRIDE + c0]);
                b[nt][1] = __float_as_uint(Bs[(ks + tg + 4) * BS_STRIDE + c0]);
            }
            #pragma unroll
            for (int mt = 0; mt < 2; mt++)
                #pragma unroll
                for (int nt = 0; nt < 4; nt++)
                    mma8(acc[mt][nt], a[mt], b[nt]);
        }
    }

    __syncthreads();
    #pragma unroll
    for (int mt = 0; mt < 2; mt++)
        #pragma unroll
        for (int nt = 0; nt < 4; nt++) {
            int r = wm * 32 + mt * 16 + gid;
            int c = wn * 32 + nt * 8 + tg * 2;
            *reinterpret_cast<float2*>(&Cs[r * CS_STRIDE + c]) =
                make_float2(acc[mt][nt][0], acc[mt][nt][1]);
            *reinterpret_cast<float2*>(&Cs[(r + 8) * CS_STRIDE + c]) =
                make_float2(acc[mt][nt][2], acc[mt][nt][3]);
        }
    __syncthreads();

    const int j16 = tid & 15;
    const int rl0 = tid >> 4;
    const int jg = (colBase >> 2) + j16;
    const float w0 = wc[jg], w1 = wc[HH + jg], w2 = wc[2 * HH + jg];
    const float4 bias = *reinterpret_cast<const float4*>(&g_bias2[colBase + j16 * 4]);

    #pragma unroll
    for (int p = 0; p < 8; p++) {
        int rl = p * 16 + rl0;
        int row = rowBase + rl;
        if (row < NN) {
            float4 v = *reinterpret_cast<const float4*>(&Cs[rl * CS_STRIDE + j16 * 4]);
            float c2 = h2[(size_t)row * HH + jg];
            float I  = sigm(v.x + bias.x + w0 * c2);
            float Fg = sigm(v.y + bias.y + w1 * c2);
            float Cn = Fg * c2 + I * tanhf(v.z + bias.z);
            float O  = sigm(v.w + bias.w + w2 * Cn);
            outC[(size_t)row * HH + jg] = Cn;
            g_hn[(size_t)row * HH + jg] = fmaxf(O * tanhf(Cn), 0.0f);
        }
    }
}

// ---------------- Linear + softmax ----------------------------------------------
__global__ void __launch_bounds__(256)
lin_softmax(const float* __restrict__ Wl, const float* __restrict__ bl)
{
    __shared__ float sW[HH * CLSN];
    __shared__ float sb[CLSN];
    __shared__ float sh[8][HH];

    int tid = threadIdx.x;
    for (int i = tid * 4; i < HH * CLSN; i += 256 * 4)
        *reinterpret_cast<float4*>(&sW[i]) = *reinterpret_cast<const float4*>(&Wl[i]);
    if (tid < CLSN) sb[tid] = bl[tid];
    int warp = tid >> 5, lane = tid & 31;
    int n = blockIdx.x * 8 + warp;
    __syncthreads();

    if (n < NN) {
        for (int k = lane; k < HH; k += 32) sh[warp][k] = g_hn[(size_t)n * HH + k];
        __syncwarp();
        float a0 = sb[lane], a1 = sb[lane + 32];
        #pragma unroll 8
        for (int k = 0; k < HH; k++) {
            float hv = sh[warp][k];
            a0 += hv * sW[k * CLSN + lane];
            a1 += hv * sW[k * CLSN + lane + 32];
        }
        float m = fmaxf(a0, a1);
        #pragma unroll
        for (int o = 16; o; o >>= 1) m = fmaxf(m, __shfl_xor_sync(0xFFFFFFFFu, m, o));
        float e0 = expf(a0 - m), e1 = expf(a1 - m);
        float s = e0 + e1;
        #pragma unroll
        for (int o = 16; o; o >>= 1) s += __shfl_xor_sync(0xFFFFFFFFu, s, o);
        float inv = 1.0f / s;
        g_z[(size_t)n * CLSN + lane]      = e0 * inv;
        g_z[(size_t)n * CLSN + lane + 32] = e1 * inv;
    }
}

// ---------------- decode --------------------------------------------------------
__global__ void decode_kernel(const int* __restrict__ s, const int* __restrict__ d,
                              float* __restrict__ r)
{
    int w = (blockIdx.x * blockDim.x + threadIdx.x) >> 5;
    int lane = threadIdx.x & 31;
    if (w >= ELE) return;
    int a = __ldg(&s[w]);
    int b = __ldg(&d[w]);
    float acc = g_z[(size_t)a * CLSN + lane]      * g_z[(size_t)b * CLSN + lane]
              + g_z[(size_t)a * CLSN + lane + 32] * g_z[(size_t)b * CLSN + lane + 32];
    #pragma unroll
    for (int o = 16; o; o >>= 1) acc += __shfl_xor_sync(0xFFFFFFFFu, acc, o);
    if (lane == 0) r[w] = acc;
}

// ---------------- copy hidden1 passthrough --------------------------------------
__global__ void copy_h1(const float* __restrict__ h1, float* __restrict__ out) {
    int i = blockIdx.x * blockDim.x + threadIdx.x;
    if (i < NN * HH / 4)
        reinterpret_cast<float4*>(out)[i] = reinterpret_cast<const float4*>(h1)[i];
}

// ================================================================================
extern "C" void kernel_launch(void* const* d_in, const int* in_sizes, int n_in,
                              void* d_out, int out_size)
{
    const float* x    = (const float*)d_in[0];
    const int*   ei   = (const int*)d_in[1];
    const int*   eli  = (const int*)d_in[2];
    const float* h1   = (const float*)d_in[3];
    const float* h2   = (const float*)d_in[4];
    const float* Wgcn = (const float*)d_in[5];
    const float* bgcn = (const float*)d_in[6];
    const float* Wx   = (const float*)d_in[7];
    const float* Th   = (const float*)d_in[8];
    const float* bgate= (const float*)d_in[9];
    const float* bconv= (const float*)d_in[10];
    const float* wc   = (const float*)d_in[11];
    const float* Wlin = (const float*)d_in[12];
    const float* blin = (const float*)d_in[13];

    float* out   = (float*)d_out;
    float* out_r = out;
    float* out_h = out + ELE;
    float* out_c = out + ELE + (size_t)NN * HH;

    const int T = 256;

    init_kernel<<<(NN + T - 1) / T, T>>>();
    deg_kernel<<<(EE + T - 1) / T, T>>>(ei + EE);
    dinv_kernel<<<(NN + T - 1) / T, T>>>();
    scan_blocks<<<SCAN_B, 1024>>>();
    scan_bases<<<1, 64>>>();
    scan_fixup<<<SCAN_B, 1024>>>();
    fill_kernel<<<(EE + T - 1) / T, T>>>(ei, ei + EE);
    {
        dim3 grid(1, MPAD / BM);
        sgemm1<<<grid, 256>>>(x, Wgcn);
    }
    pack_B2<<<(KCAT * NG + T - 1) / T, T>>>(Wx, Th, bgate, bconv);
    gather_kernel<<<(NN * 16 + T - 1) / T, T>>>(bgcn, h1);
    {
        dim3 grid(NG / 64, MPAD / 128);
        gemm2_gates<<<grid, 256>>>(h2, wc, out_c);
    }
    lin_softmax<<<(NN + 7) / 8, 256>>>(Wlin, blin);
    decode_kernel<<<(ELE * 32 + T - 1) / T, T>>>(eli, eli + ELE, out_r);
    copy_h1<<<(NN * HH / 4 + T - 1) / T, T>>>(h1, out_h);
}

// round 6
// speedup vs baseline: 1.3676x; 1.1271x over previous
#include <cuda_runtime.h>
#include <math.h>
#include <stdint.h>

// Problem constants (fixed by the reference)
#define NN   50000      // nodes
#define FF   64         // node features
#define HH   128        // hidden
#define CLSN 64         // classes
#define EE   800000     // edges
#define ELE  200000     // label edges
#define MPAD 50048      // 391 * 128, padded M (no row guards on scratch)
#define KCAT 192        // FF + HH
#define NG   512        // 4*HH

#define SCAN_B 49       // ceil(NN / 1024)

// ---------------- scratch (device globals: allocation-free, zero-initialized) ----
__device__ float g_deg  [MPAD];
__device__ float g_dinv [MPAD];
__device__ int   g_off  [MPAD];                 // CSR row offsets (by dst)
__device__ int   g_cur  [MPAD];                 // fill cursors
__device__ int   g_bsum [64];                   // per-block totals
__device__ int   g_bbase[64];                   // exclusive block bases
__device__ int   g_esrc [EE];                   // CSR: src per slot
__device__ float g_abuf [(size_t)MPAD * KCAT];  // [Ax | hidden1], tf32-rounded
__device__ float g_B2   [KCAT * NG];            // [W_gcn@Wx ; Th], gate-interleaved, tf32
__device__ float g_bias2[NG];                   // b_gate + b_conv + b_gcn@Wx, interleaved
__device__ float g_hn   [(size_t)MPAD * HH];    // relu(H_new)
__device__ float g_z    [(size_t)MPAD * CLSN];  // softmax output

__device__ __forceinline__ float sigm(float x) { return 1.0f / (1.0f + expf(-x)); }

__device__ __forceinline__ float to_tf32(float x) {
    uint32_t o;
    asm("cvt.rna.tf32.f32 %0, %1;" : "=r"(o) : "f"(x));
    return __uint_as_float(o);
}

// ---------------- init: deg = 1 (self loop) -------------------------------------
__global__ void init_kernel() {
    int i = blockIdx.x * blockDim.x + threadIdx.x;
    if (i < NN) g_deg[i] = 1.0f;
}

__global__ void deg_kernel(const int* __restrict__ dst) {
    int e = blockIdx.x * blockDim.x + threadIdx.x;
    if (e < EE) atomicAdd(&g_deg[dst[e]], 1.0f);
}

// ---------------- parallel 3-pass exclusive scan (+ dinv fused) ------------------
__global__ void __launch_bounds__(1024)
scan_blocks() {
    __shared__ int wsum[32];
    int t = threadIdx.x, i = blockIdx.x * 1024 + t;
    int lane = t & 31, warp = t >> 5;
    float dg = (i < NN) ? g_deg[i] : 1.0f;
    if (i < NN) g_dinv[i] = rsqrtf(dg);          // fused dinv
    int cnt = (i < NN) ? ((int)dg - 1) : 0;

    int inc = cnt;
    #pragma unroll
    for (int o = 1; o < 32; o <<= 1) {
        int v = __shfl_up_sync(0xFFFFFFFFu, inc, o);
        if (lane >= o) inc += v;
    }
    if (lane == 31) wsum[warp] = inc;
    __syncthreads();
    if (warp == 0) {
        int w = wsum[lane];
        #pragma unroll
        for (int o = 1; o < 32; o <<= 1) {
            int v = __shfl_up_sync(0xFFFFFFFFu, w, o);
            if (lane >= o) w += v;
        }
        wsum[lane] = w;
        if (lane == 31) g_bsum[blockIdx.x] = w;
    }
    __syncthreads();
    int base = (warp > 0) ? wsum[warp - 1] : 0;
    if (i < NN) g_off[i] = base + inc - cnt;
}

__global__ void __launch_bounds__(64)
scan_bases() {
    __shared__ int s[64];
    int t = threadIdx.x;
    s[t] = (t < SCAN_B) ? g_bsum[t] : 0;
    __syncthreads();
    #pragma unroll
    for (int o = 1; o < 64; o <<= 1) {
        int v = (t >= o) ? s[t - o] : 0;
        __syncthreads();
        s[t] += v;
        __syncthreads();
    }
    if (t < SCAN_B) g_bbase[t] = s[t] - g_bsum[t];
}

__global__ void __launch_bounds__(1024)
scan_fixup() {
    int i = blockIdx.x * 1024 + threadIdx.x;
    if (i < NN) {
        int o = g_off[i] + g_bbase[blockIdx.x];
        g_off[i] = o;
        g_cur[i] = o;
    }
}

// ---------------- CSR fill ------------------------------------------------------
__global__ void fill_kernel(const int* __restrict__ src, const int* __restrict__ dst) {
    int e = blockIdx.x * blockDim.x + threadIdx.x;
    if (e >= EE) return;
    int slot = atomicAdd(&g_cur[dst[e]], 1);
    g_esrc[slot] = src[e];
}

// ---------------- gather on raw x: abuf = [ (Ax) | hidden1 ], tf32 ----------------
__global__ void __launch_bounds__(256)
gather_kernel(const float* __restrict__ x, const float* __restrict__ h1)
{
    int t = blockIdx.x * blockDim.x + threadIdx.x;
    int n = t >> 4, lane = t & 15;
    if (n >= NN) return;

    const float4* x4 = reinterpret_cast<const float4*>(x);
    int beg = g_off[n];
    int cnt = (int)g_deg[n] - 1;

    float4 acc = make_float4(0.f, 0.f, 0.f, 0.f);
    for (int i = beg; i < beg + cnt; i++) {
        int s = __ldg(&g_esrc[i]);
        float w = __ldg(&g_dinv[s]);
        float4 v = __ldg(&x4[(size_t)s * 16 + lane]);
        acc.x += w * v.x; acc.y += w * v.y; acc.z += w * v.z; acc.w += w * v.w;
    }
    float dn = g_dinv[n];
    float4 self = x4[(size_t)n * 16 + lane];
    float4 h;
    h.x = to_tf32(dn * acc.x + dn * dn * self.x);
    h.y = to_tf32(dn * acc.y + dn * dn * self.y);
    h.z = to_tf32(dn * acc.z + dn * dn * self.z);
    h.w = to_tf32(dn * acc.w + dn * dn * self.w);
    *reinterpret_cast<float4*>(&g_abuf[(size_t)n * KCAT + lane * 4]) = h;

    const float4* h14 = reinterpret_cast<const float4*>(h1);
    #pragma unroll
    for (int q = 0; q < 2; q++) {
        float4 v = __ldg(&h14[(size_t)n * 32 + lane * 2 + q]);
        v.x = to_tf32(v.x); v.y = to_tf32(v.y); v.z = to_tf32(v.z); v.w = to_tf32(v.w);
        *reinterpret_cast<float4*>(&g_abuf[(size_t)n * KCAT + FF + lane * 8 + q * 4]) = v;
    }
}

// ---------------- pack B2: rows 0..63 = W_gcn@Wx, rows 64..191 = Th --------------
// gate-interleaved columns (new col = 4j+g <=> old col = g*128+j), tf32-rounded
__global__ void pack_B2(const float* __restrict__ Wgcn, const float* __restrict__ Wx,
                        const float* __restrict__ Th,
                        const float* __restrict__ bgate, const float* __restrict__ bconv,
                        const float* __restrict__ bgcn)
{
    int i = blockIdx.x * blockDim.x + threadIdx.x;
    if (i >= KCAT * NG) return;
    int k = i / NG, col = i - k * NG;
    int j = col >> 2, g = col & 3;
    int old = g * HH + j;
    float v;
    if (k < FF) {
        float s = 0.0f;
        #pragma unroll 8
        for (int q = 0; q < FF; q++)
            s += Wgcn[k * FF + q] * Wx[(size_t)q * NG + old];
        v = s;
    } else {
        v = Th[(size_t)(k - FF) * NG + old];
    }
    g_B2[i] = to_tf32(v);
    if (i < NG) {
        float s = bgate[old] + bconv[old];
        #pragma unroll 8
        for (int q = 0; q < FF; q++)
            s += bgcn[q] * Wx[(size_t)q * NG + old];
        g_bias2[i] = s;
    }
}

// ---------------- tf32 MMA GEMM2 (128x128 tiles) + shuffle gate epilogue ---------
#define AS_STRIDE 36    // bank = (4*r + k) % 32 -> conflict-free A frag reads
#define BS_STRIDE 136   // 136 % 32 == 8 -> bank = (8*tg + gid) distinct

__device__ __forceinline__ void mma8(float* c, const uint32_t* a, const uint32_t* b) {
    asm volatile("mma.sync.aligned.m16n8k8.row.col.f32.tf32.tf32.f32 "
        "{%0,%1,%2,%3}, {%4,%5,%6,%7}, {%8,%9}, {%0,%1,%2,%3};"
        : "+f"(c[0]), "+f"(c[1]), "+f"(c[2]), "+f"(c[3])
        : "r"(a[0]), "r"(a[1]), "r"(a[2]), "r"(a[3]), "r"(b[0]), "r"(b[1]));
}

__global__ void __launch_bounds__(512)
gemm2_gates(const float* __restrict__ h2, const float* __restrict__ wc,
            float* __restrict__ outC)
{
    __shared__ __align__(16) float As[128 * AS_STRIDE];   // 18.4 KB
    __shared__ __align__(16) float Bs[32 * BS_STRIDE];    // 17.4 KB

    const int tid  = threadIdx.x;
    const int lane = tid & 31, warp = tid >> 5;
    const int wm = warp & 3, wn = warp >> 2;      // 4 M-warps x 4 N-warps
    const int gid = lane >> 2, tg = lane & 3;
    const int rowBase = blockIdx.y * 128;
    const int colBase = blockIdx.x * 128;

    // prefetch mapping: A 128x32 (1024 f4, 2/thread), B 32x128 (1024 f4, 2/thread)
    const int am = tid >> 3, ak4 = (tid & 7) << 2;
    const int bk = tid >> 5, bn4 = (tid & 31) << 2;
    const float* aptr = &g_abuf[(size_t)(rowBase + am) * KCAT + ak4];
    const float* bptr = &g_B2[(size_t)bk * NG + colBase + bn4];

    float acc[2][4][4];
    #pragma unroll
    for (int mt = 0; mt < 2; mt++)
        #pragma unroll
        for (int nt = 0; nt < 4; nt++)
            #pragma unroll
            for (int r = 0; r < 4; r++) acc[mt][nt][r] = 0.0f;

    float4 ra[2], rb[2];
    ra[0] = *reinterpret_cast<const float4*>(aptr);
    ra[1] = *reinterpret_cast<const float4*>(aptr + (size_t)64 * KCAT);
    rb[0] = *reinterpret_cast<const float4*>(bptr);
    rb[1] = *reinterpret_cast<const float4*>(bptr + (size_t)16 * NG);

    #pragma unroll
    for (int c = 0; c < 6; c++) {
        __syncthreads();
        *reinterpret_cast<float4*>(&As[am * AS_STRIDE + ak4]) = ra[0];
        *reinterpret_cast<float4*>(&As[(am + 64) * AS_STRIDE + ak4]) = ra[1];
        *reinterpret_cast<float4*>(&Bs[bk * BS_STRIDE + bn4]) = rb[0];
        *reinterpret_cast<float4*>(&Bs[(bk + 16) * BS_STRIDE + bn4]) = rb[1];
        __syncthreads();

        if (c < 5) {
            int kc = (c + 1) * 32;
            ra[0] = *reinterpret_cast<const float4*>(aptr + kc);
            ra[1] = *reinterpret_cast<const float4*>(aptr + (size_t)64 * KCAT + kc);
            rb[0] = *reinterpret_cast<const float4*>(bptr + (size_t)kc * NG);
            rb[1] = *reinterpret_cast<const float4*>(bptr + (size_t)(kc + 16) * NG);
        }

        #pragma unroll
        for (int ks = 0; ks < 32; ks += 8) {
            uint32_t a[2][4], b[4][2];
            #pragma unroll
            for (int mt = 0; mt < 2; mt++) {
                int r0 = wm * 32 + mt * 16 + gid;
                a[mt][0] = __float_as_uint(As[r0 * AS_STRIDE + ks + tg]);
                a[mt][1] = __float_as_uint(As[(r0 + 8) * AS_STRIDE + ks + tg]);
                a[mt][2] = __float_as_uint(As[r0 * AS_STRIDE + ks + tg + 4]);
                a[mt][3] = __float_as_uint(As[(r0 + 8) * AS_STRIDE + ks + tg + 4]);
            }
            #pragma unroll
            for (int nt = 0; nt < 4; nt++) {
                int c0 = wn * 32 + nt * 8 + gid;
                b[nt][0] = __float_as_uint(Bs[(ks + tg) * BS_STRIDE + c0]);
                b[nt][1] = __float_as_uint(Bs[(ks + tg + 4) * BS_STRIDE + c0]);
            }
            #pragma unroll
            for (int mt = 0; mt < 2; mt++)
                #pragma unroll
                for (int nt = 0; nt < 4; nt++)
                    mma8(acc[mt][nt], a[mt], b[nt]);
        }
    }

    // shuffle-based gate epilogue: lane pairs (lane^1) exchange gate halves.
    // fragment: c0,c1 = (row gid, cols 2tg, 2tg+1); c2,c3 = (row gid+8, same cols).
    // even tg holds (i,f) of hidden j, odd tg holds (c,o) of the same j.
    #pragma unroll
    for (int nt = 0; nt < 4; nt++) {
        int col = colBase + wn * 32 + nt * 8 + tg * 2;
        int j = col >> 2;
        float4 b4 = *reinterpret_cast<const float4*>(&g_bias2[j * 4]);
        float w0 = wc[j], w1 = wc[HH + j], w2 = wc[2 * HH + j];
        #pragma unroll
        for (int mt = 0; mt < 2; mt++) {
            float c0 = acc[mt][nt][0], c1 = acc[mt][nt][1];
            float c2 = acc[mt][nt][2], c3 = acc[mt][nt][3];
            float v0 = __shfl_xor_sync(0xFFFFFFFFu, c0, 1);
            float v1 = __shfl_xor_sync(0xFFFFFFFFu, c1, 1);
            float v2 = __shfl_xor_sync(0xFFFFFFFFu, c2, 1);
            float v3 = __shfl_xor_sync(0xFFFFFFFFu, c3, 1);
            int R = rowBase + wm * 32 + mt * 16;
            int row;
            float gi, gf, gc, go;
            if (!(tg & 1)) { row = R + gid;     gi = c0; gf = c1; gc = v0; go = v1; }
            else           { row = R + gid + 8; gi = v2; gf = v3; gc = c2; go = c3; }
            if (row < NN) {
                float cc = h2[(size_t)row * HH + j];
                float I  = sigm(gi + b4.x + w0 * cc);
                float Fg = sigm(gf + b4.y + w1 * cc);
                float Cn = Fg * cc + I * tanhf(gc + b4.z);
                float O  = sigm(go + b4.w + w2 * Cn);
                outC[(size_t)row * HH + j] = Cn;
                g_hn[(size_t)row * HH + j] = fmaxf(O * tanhf(Cn), 0.0f);
            }
        }
    }
}

// ---------------- Linear + softmax ----------------------------------------------
__global__ void __launch_bounds__(256)
lin_softmax(const float* __restrict__ Wl, const float* __restrict__ bl)
{
    __shared__ float sW[HH * CLSN];
    __shared__ float sb[CLSN];
    __shared__ float sh[8][HH];

    int tid = threadIdx.x;
    for (int i = tid * 4; i < HH * CLSN; i += 256 * 4)
        *reinterpret_cast<float4*>(&sW[i]) = *reinterpret_cast<const float4*>(&Wl[i]);
    if (tid < CLSN) sb[tid] = bl[tid];
    int warp = tid >> 5, lane = tid & 31;
    int n = blockIdx.x * 8 + warp;
    __syncthreads();

    if (n < NN) {
        for (int k = lane; k < HH; k += 32) sh[warp][k] = g_hn[(size_t)n * HH + k];
        __syncwarp();
        float a0 = sb[lane], a1 = sb[lane + 32];
        #pragma unroll 8
        for (int k = 0; k < HH; k++) {
            float hv = sh[warp][k];
            a0 += hv * sW[k * CLSN + lane];
            a1 += hv * sW[k * CLSN + lane + 32];
        }
        float m = fmaxf(a0, a1);
        #pragma unroll
        for (int o = 16; o; o >>= 1) m = fmaxf(m, __shfl_xor_sync(0xFFFFFFFFu, m, o));
        float e0 = expf(a0 - m), e1 = expf(a1 - m);
        float s = e0 + e1;
        #pragma unroll
        for (int o = 16; o; o >>= 1) s += __shfl_xor_sync(0xFFFFFFFFu, s, o);
        float inv = 1.0f / s;
        g_z[(size_t)n * CLSN + lane]      = e0 * inv;
        g_z[(size_t)n * CLSN + lane + 32] = e1 * inv;
    }
}

// ---------------- decode --------------------------------------------------------
__global__ void decode_kernel(const int* __restrict__ s, const int* __restrict__ d,
                              float* __restrict__ r)
{
    int w = (blockIdx.x * blockDim.x + threadIdx.x) >> 5;
    int lane = threadIdx.x & 31;
    if (w >= ELE) return;
    int a = __ldg(&s[w]);
    int b = __ldg(&d[w]);
    float acc = g_z[(size_t)a * CLSN + lane]      * g_z[(size_t)b * CLSN + lane]
              + g_z[(size_t)a * CLSN + lane + 32] * g_z[(size_t)b * CLSN + lane + 32];
    #pragma unroll
    for (int o = 16; o; o >>= 1) acc += __shfl_xor_sync(0xFFFFFFFFu, acc, o);
    if (lane == 0) r[w] = acc;
}

// ---------------- copy hidden1 passthrough --------------------------------------
__global__ void copy_h1(const float* __restrict__ h1, float* __restrict__ out) {
    int i = blockIdx.x * blockDim.x + threadIdx.x;
    if (i < NN * HH / 4)
        reinterpret_cast<float4*>(out)[i] = reinterpret_cast<const float4*>(h1)[i];
}

// ================================================================================
extern "C" void kernel_launch(void* const* d_in, const int* in_sizes, int n_in,
                              void* d_out, int out_size)
{
    const float* x    = (const float*)d_in[0];
    const int*   ei   = (const int*)d_in[1];
    const int*   eli  = (const int*)d_in[2];
    const float* h1   = (const float*)d_in[3];
    const float* h2   = (const float*)d_in[4];
    const float* Wgcn = (const float*)d_in[5];
    const float* bgcn = (const float*)d_in[6];
    const float* Wx   = (const float*)d_in[7];
    const float* Th   = (const float*)d_in[8];
    const float* bgate= (const float*)d_in[9];
    const float* bconv= (const float*)d_in[10];
    const float* wc   = (const float*)d_in[11];
    const float* Wlin = (const float*)d_in[12];
    const float* blin = (const float*)d_in[13];

    float* out   = (float*)d_out;
    float* out_r = out;
    float* out_h = out + ELE;
    float* out_c = out + ELE + (size_t)NN * HH;

    const int T = 256;

    init_kernel<<<(NN + T - 1) / T, T>>>();
    deg_kernel<<<(EE + T - 1) / T, T>>>(ei + EE);
    scan_blocks<<<SCAN_B, 1024>>>();
    scan_bases<<<1, 64>>>();
    scan_fixup<<<SCAN_B, 1024>>>();
    fill_kernel<<<(EE + T - 1) / T, T>>>(ei, ei + EE);
    pack_B2<<<(KCAT * NG + T - 1) / T, T>>>(Wgcn, Wx, Th, bgate, bconv, bgcn);
    gather_kernel<<<(NN * 16 + T - 1) / T, T>>>(x, h1);
    {
        dim3 grid(NG / 128, MPAD / 128);
        gemm2_gates<<<grid, 512>>>(h2, wc, out_c);
    }
    lin_softmax<<<(NN + 7) / 8, 256>>>(Wlin, blin);
    decode_kernel<<<(ELE * 32 + T - 1) / T, T>>>(eli, eli + ELE, out_r);
    copy_h1<<<(NN * HH / 4 + T - 1) / T, T>>>(h1, out_h);
}

// round 7
// speedup vs baseline: 1.3761x; 1.0062x over previous
#include <cuda_runtime.h>
#include <math.h>
#include <stdint.h>

// Problem constants (fixed by the reference)
#define NN   50000      // nodes
#define FF   64         // node features
#define HH   128        // hidden
#define CLSN 64         // classes
#define EE   800000     // edges
#define ELE  200000     // label edges
#define MPAD 50048      // 391 * 128, padded M (no row guards on scratch)
#define KCAT 192        // FF + HH
#define NG   512        // 4*HH

#define SCAN_B 49       // ceil(NN / 1024)

// ---------------- scratch (device globals: allocation-free, zero-initialized) ----
__device__ float g_deg  [MPAD];
__device__ float g_dinv [MPAD];
__device__ int   g_off  [MPAD];                 // CSR row offsets (by dst)
__device__ int   g_cur  [MPAD];                 // fill cursors
__device__ int   g_bsum [64];                   // per-block totals
__device__ int   g_bbase[64];                   // exclusive block bases
__device__ int   g_esrc [EE];                   // CSR: src per slot
__device__ float g_abuf [(size_t)MPAD * KCAT];  // [Ax | hidden1], tf32-rounded
__device__ float g_B2   [KCAT * NG];            // [W_gcn@Wx ; Th], gate-interleaved, tf32
__device__ float g_bias2[NG];                   // b_gate + b_conv + b_gcn@Wx, interleaved
__device__ float g_hn   [(size_t)MPAD * HH];    // relu(H_new)
__device__ float g_z    [(size_t)MPAD * CLSN];  // softmax output

__device__ __forceinline__ float sigm(float x) { return 1.0f / (1.0f + expf(-x)); }

__device__ __forceinline__ float to_tf32(float x) {
    uint32_t o;
    asm("cvt.rna.tf32.f32 %0, %1;" : "=r"(o) : "f"(x));
    return __uint_as_float(o);
}

// ---------------- init: deg = 1 (self loop) -------------------------------------
__global__ void init_kernel() {
    int i = blockIdx.x * blockDim.x + threadIdx.x;
    if (i < NN) g_deg[i] = 1.0f;
}

__global__ void deg_kernel(const int* __restrict__ dst) {
    int e = blockIdx.x * blockDim.x + threadIdx.x;
    if (e < EE) atomicAdd(&g_deg[dst[e]], 1.0f);
}

// ---------------- parallel 3-pass exclusive scan (+ dinv fused) ------------------
__global__ void __launch_bounds__(1024)
scan_blocks() {
    __shared__ int wsum[32];
    int t = threadIdx.x, i = blockIdx.x * 1024 + t;
    int lane = t & 31, warp = t >> 5;
    float dg = (i < NN) ? g_deg[i] : 1.0f;
    if (i < NN) g_dinv[i] = rsqrtf(dg);          // fused dinv
    int cnt = (i < NN) ? ((int)dg - 1) : 0;

    int inc = cnt;
    #pragma unroll
    for (int o = 1; o < 32; o <<= 1) {
        int v = __shfl_up_sync(0xFFFFFFFFu, inc, o);
        if (lane >= o) inc += v;
    }
    if (lane == 31) wsum[warp] = inc;
    __syncthreads();
    if (warp == 0) {
        int w = wsum[lane];
        #pragma unroll
        for (int o = 1; o < 32; o <<= 1) {
            int v = __shfl_up_sync(0xFFFFFFFFu, w, o);
            if (lane >= o) w += v;
        }
        wsum[lane] = w;
        if (lane == 31) g_bsum[blockIdx.x] = w;
    }
    __syncthreads();
    int base = (warp > 0) ? wsum[warp - 1] : 0;
    if (i < NN) g_off[i] = base + inc - cnt;
}

__global__ void __launch_bounds__(64)
scan_bases() {
    __shared__ int s[64];
    int t = threadIdx.x;
    s[t] = (t < SCAN_B) ? g_bsum[t] : 0;
    __syncthreads();
    #pragma unroll
    for (int o = 1; o < 64; o <<= 1) {
        int v = (t >= o) ? s[t - o] : 0;
        __syncthreads();
        s[t] += v;
        __syncthreads();
    }
    if (t < SCAN_B) g_bbase[t] = s[t] - g_bsum[t];
}

__global__ void __launch_bounds__(1024)
scan_fixup() {
    int i = blockIdx.x * 1024 + threadIdx.x;
    if (i < NN) {
        int o = g_off[i] + g_bbase[blockIdx.x];
        g_off[i] = o;
        g_cur[i] = o;
    }
}

// ---------------- CSR fill ------------------------------------------------------
__global__ void fill_kernel(const int* __restrict__ src, const int* __restrict__ dst) {
    int e = blockIdx.x * blockDim.x + threadIdx.x;
    if (e >= EE) return;
    int slot = atomicAdd(&g_cur[dst[e]], 1);
    g_esrc[slot] = src[e];
}

// ---------------- gather on raw x: abuf = [ (Ax) | hidden1 ], tf32 ----------------
__global__ void __launch_bounds__(256)
gather_kernel(const float* __restrict__ x, const float* __restrict__ h1)
{
    int t = blockIdx.x * blockDim.x + threadIdx.x;
    int n = t >> 4, lane = t & 15;
    if (n >= NN) return;

    const float4* x4 = reinterpret_cast<const float4*>(x);
    int beg = g_off[n];
    int cnt = (int)g_deg[n] - 1;

    float4 acc = make_float4(0.f, 0.f, 0.f, 0.f);
    for (int i = beg; i < beg + cnt; i++) {
        int s = __ldg(&g_esrc[i]);
        float w = __ldg(&g_dinv[s]);
        float4 v = __ldg(&x4[(size_t)s * 16 + lane]);
        acc.x += w * v.x; acc.y += w * v.y; acc.z += w * v.z; acc.w += w * v.w;
    }
    float dn = g_dinv[n];
    float4 self = x4[(size_t)n * 16 + lane];
    float4 h;
    h.x = to_tf32(dn * acc.x + dn * dn * self.x);
    h.y = to_tf32(dn * acc.y + dn * dn * self.y);
    h.z = to_tf32(dn * acc.z + dn * dn * self.z);
    h.w = to_tf32(dn * acc.w + dn * dn * self.w);
    *reinterpret_cast<float4*>(&g_abuf[(size_t)n * KCAT + lane * 4]) = h;

    const float4* h14 = reinterpret_cast<const float4*>(h1);
    #pragma unroll
    for (int q = 0; q < 2; q++) {
        float4 v = __ldg(&h14[(size_t)n * 32 + lane * 2 + q]);
        v.x = to_tf32(v.x); v.y = to_tf32(v.y); v.z = to_tf32(v.z); v.w = to_tf32(v.w);
        *reinterpret_cast<float4*>(&g_abuf[(size_t)n * KCAT + FF + lane * 8 + q * 4]) = v;
    }
}

// ---------------- pack B2: rows 0..63 = W_gcn@Wx, rows 64..191 = Th --------------
// gate-interleaved columns (new col = 4j+g <=> old col = g*128+j), tf32-rounded
__global__ void pack_B2(const float* __restrict__ Wgcn, const float* __restrict__ Wx,
                        const float* __restrict__ Th,
                        const float* __restrict__ bgate, const float* __restrict__ bconv,
                        const float* __restrict__ bgcn)
{
    int i = blockIdx.x * blockDim.x + threadIdx.x;
    if (i >= KCAT * NG) return;
    int k = i / NG, col = i - k * NG;
    int j = col >> 2, g = col & 3;
    int old = g * HH + j;
    float v;
    if (k < FF) {
        float s = 0.0f;
        #pragma unroll 8
        for (int q = 0; q < FF; q++)
            s += Wgcn[k * FF + q] * Wx[(size_t)q * NG + old];
        v = s;
    } else {
        v = Th[(size_t)(k - FF) * NG + old];
    }
    g_B2[i] = to_tf32(v);
    if (i < NG) {
        float s = bgate[old] + bconv[old];
        #pragma unroll 8
        for (int q = 0; q < FF; q++)
            s += bgcn[q] * Wx[(size_t)q * NG + old];
        g_bias2[i] = s;
    }
}

// ---------------- tf32 MMA GEMM2 (128x128 tiles) + shuffle gate epilogue ---------
#define AS_STRIDE 36    // bank = (4*r + k) % 32 -> conflict-free A frag reads
#define BS_STRIDE 136   // 136 % 32 == 8 -> bank = (8*tg + gid) distinct

__device__ __forceinline__ void mma8(float* c, const uint32_t* a, const uint32_t* b) {
    asm volatile("mma.sync.aligned.m16n8k8.row.col.f32.tf32.tf32.f32 "
        "{%0,%1,%2,%3}, {%4,%5,%6,%7}, {%8,%9}, {%0,%1,%2,%3};"
        : "+f"(c[0]), "+f"(c[1]), "+f"(c[2]), "+f"(c[3])
        : "r"(a[0]), "r"(a[1]), "r"(a[2]), "r"(a[3]), "r"(b[0]), "r"(b[1]));
}

__global__ void __launch_bounds__(512)
gemm2_gates(const float* __restrict__ h2, const float* __restrict__ wc,
            float* __restrict__ outC)
{
    __shared__ __align__(16) float As[128 * AS_STRIDE];   // 18.4 KB
    __shared__ __align__(16) float Bs[32 * BS_STRIDE];    // 17.4 KB

    const int tid  = threadIdx.x;
    const int lane = tid & 31, warp = tid >> 5;
    const int wm = warp & 3, wn = warp >> 2;      // 4 M-warps x 4 N-warps
    const int gid = lane >> 2, tg = lane & 3;
    const int rowBase = blockIdx.y * 128;
    const int colBase = blockIdx.x * 128;

    // prefetch mapping: A 128x32 (1024 f4, 2/thread), B 32x128 (1024 f4, 2/thread)
    const int am = tid >> 3, ak4 = (tid & 7) << 2;
    const int bk = tid >> 5, bn4 = (tid & 31) << 2;
    const float* aptr = &g_abuf[(size_t)(rowBase + am) * KCAT + ak4];
    const float* bptr = &g_B2[(size_t)bk * NG + colBase + bn4];

    float acc[2][4][4];
    #pragma unroll
    for (int mt = 0; mt < 2; mt++)
        #pragma unroll
        for (int nt = 0; nt < 4; nt++)
            #pragma unroll
            for (int r = 0; r < 4; r++) acc[mt][nt][r] = 0.0f;

    float4 ra[2], rb[2];
    ra[0] = *reinterpret_cast<const float4*>(aptr);
    ra[1] = *reinterpret_cast<const float4*>(aptr + (size_t)64 * KCAT);
    rb[0] = *reinterpret_cast<const float4*>(bptr);
    rb[1] = *reinterpret_cast<const float4*>(bptr + (size_t)16 * NG);

    #pragma unroll
    for (int c = 0; c < 6; c++) {
        __syncthreads();
        *reinterpret_cast<float4*>(&As[am * AS_STRIDE + ak4]) = ra[0];
        *reinterpret_cast<float4*>(&As[(am + 64) * AS_STRIDE + ak4]) = ra[1];
        *reinterpret_cast<float4*>(&Bs[bk * BS_STRIDE + bn4]) = rb[0];
        *reinterpret_cast<float4*>(&Bs[(bk + 16) * BS_STRIDE + bn4]) = rb[1];
        __syncthreads();

        if (c < 5) {
            int kc = (c + 1) * 32;
            ra[0] = *reinterpret_cast<const float4*>(aptr + kc);
            ra[1] = *reinterpret_cast<const float4*>(aptr + (size_t)64 * KCAT + kc);
            rb[0] = *reinterpret_cast<const float4*>(bptr + (size_t)kc * NG);
            rb[1] = *reinterpret_cast<const float4*>(bptr + (size_t)(kc + 16) * NG);
        }

        #pragma unroll
        for (int ks = 0; ks < 32; ks += 8) {
            uint32_t a[2][4], b[4][2];
            #pragma unroll
            for (int mt = 0; mt < 2; mt++) {
                int r0 = wm * 32 + mt * 16 + gid;
                a[mt][0] = __float_as_uint(As[r0 * AS_STRIDE + ks + tg]);
                a[mt][1] = __float_as_uint(As[(r0 + 8) * AS_STRIDE + ks + tg]);
                a[mt][2] = __float_as_uint(As[r0 * AS_STRIDE + ks + tg + 4]);
                a[mt][3] = __float_as_uint(As[(r0 + 8) * AS_STRIDE + ks + tg + 4]);
            }
            #pragma unroll
            for (int nt = 0; nt < 4; nt++) {
                int c0 = wn * 32 + nt * 8 + gid;
                b[nt][0] = __float_as_uint(Bs[(ks + tg) * BS_STRIDE + c0]);
                b[nt][1] = __float_as_uint(Bs[(ks + tg + 4) * BS_STRIDE + c0]);
            }
            #pragma unroll
            for (int mt = 0; mt < 2; mt++)
                #pragma unroll
                for (int nt = 0; nt < 4; nt++)
                    mma8(acc[mt][nt], a[mt], b[nt]);
        }
    }

    // shuffle-based gate epilogue: lane pairs (lane^1) exchange gate halves.
    // fragment: c0,c1 = (row gid, cols 2tg, 2tg+1); c2,c3 = (row gid+8, same cols).
    // even tg holds (i,f) of hidden j, odd tg holds (c,o) of the same j.
    #pragma unroll
    for (int nt = 0; nt < 4; nt++) {
        int col = colBase + wn * 32 + nt * 8 + tg * 2;
        int j = col >> 2;
        float4 b4 = *reinterpret_cast<const float4*>(&g_bias2[j * 4]);
        float w0 = wc[j], w1 = wc[HH + j], w2 = wc[2 * HH + j];
        #pragma unroll
        for (int mt = 0; mt < 2; mt++) {
            float c0 = acc[mt][nt][0], c1 = acc[mt][nt][1];
            float c2 = acc[mt][nt][2], c3 = acc[mt][nt][3];
            float v0 = __shfl_xor_sync(0xFFFFFFFFu, c0, 1);
            float v1 = __shfl_xor_sync(0xFFFFFFFFu, c1, 1);
            float v2 = __shfl_xor_sync(0xFFFFFFFFu, c2, 1);
            float v3 = __shfl_xor_sync(0xFFFFFFFFu, c3, 1);
            int R = rowBase + wm * 32 + mt * 16;
            int row;
            float gi, gf, gc, go;
            if (!(tg & 1)) { row = R + gid;     gi = c0; gf = c1; gc = v0; go = v1; }
            else           { row = R + gid + 8; gi = v2; gf = v3; gc = c2; go = c3; }
            if (row < NN) {
                float cc = h2[(size_t)row * HH + j];
                float I  = sigm(gi + b4.x + w0 * cc);
                float Fg = sigm(gf + b4.y + w1 * cc);
                float Cn = Fg * cc + I * tanhf(gc + b4.z);
                float O  = sigm(go + b4.w + w2 * Cn);
                outC[(size_t)row * HH + j] = Cn;
                g_hn[(size_t)row * HH + j] = fmaxf(O * tanhf(Cn), 0.0f);
            }
        }
    }
}

// ---------------- Linear + softmax ----------------------------------------------
__global__ void __launch_bounds__(256)
lin_softmax(const float* __restrict__ Wl, const float* __restrict__ bl)
{
    __shared__ float sW[HH * CLSN];
    __shared__ float sb[CLSN];
    __shared__ float sh[8][HH];

    int tid = threadIdx.x;
    for (int i = tid * 4; i < HH * CLSN; i += 256 * 4)
        *reinterpret_cast<float4*>(&sW[i]) = *reinterpret_cast<const float4*>(&Wl[i]);
    if (tid < CLSN) sb[tid] = bl[tid];
    int warp = tid >> 5, lane = tid & 31;
    int n = blockIdx.x * 8 + warp;
    __syncthreads();

    if (n < NN) {
        for (int k = lane; k < HH; k += 32) sh[warp][k] = g_hn[(size_t)n * HH + k];
        __syncwarp();
        float a0 = sb[lane], a1 = sb[lane + 32];
        #pragma unroll 8
        for (int k = 0; k < HH; k++) {
            float hv = sh[warp][k];
            a0 += hv * sW[k * CLSN + lane];
            a1 += hv * sW[k * CLSN + lane + 32];
        }
        float m = fmaxf(a0, a1);
        #pragma unroll
        for (int o = 16; o; o >>= 1) m = fmaxf(m, __shfl_xor_sync(0xFFFFFFFFu, m, o));
        float e0 = expf(a0 - m), e1 = expf(a1 - m);
        float s = e0 + e1;
        #pragma unroll
        for (int o = 16; o; o >>= 1) s += __shfl_xor_sync(0xFFFFFFFFu, s, o);
        float inv = 1.0f / s;
        g_z[(size_t)n * CLSN + lane]      = e0 * inv;
        g_z[(size_t)n * CLSN + lane + 32] = e1 * inv;
    }
}

// ---------------- decode --------------------------------------------------------
__global__ void decode_kernel(const int* __restrict__ s, const int* __restrict__ d,
                              float* __restrict__ r)
{
    int w = (blockIdx.x * blockDim.x + threadIdx.x) >> 5;
    int lane = threadIdx.x & 31;
    if (w >= ELE) return;
    int a = __ldg(&s[w]);
    int b = __ldg(&d[w]);
    float acc = g_z[(size_t)a * CLSN + lane]      * g_z[(size_t)b * CLSN + lane]
              + g_z[(size_t)a * CLSN + lane + 32] * g_z[(size_t)b * CLSN + lane + 32];
    #pragma unroll
    for (int o = 16; o; o >>= 1) acc += __shfl_xor_sync(0xFFFFFFFFu, acc, o);
    if (lane == 0) r[w] = acc;
}

// ---------------- copy hidden1 passthrough --------------------------------------
__global__ void copy_h1(const float* __restrict__ h1, float* __restrict__ out) {
    int i = blockIdx.x * blockDim.x + threadIdx.x;
    if (i < NN * HH / 4)
        reinterpret_cast<float4*>(out)[i] = reinterpret_cast<const float4*>(h1)[i];
}

// ================================================================================
extern "C" void kernel_launch(void* const* d_in, const int* in_sizes, int n_in,
                              void* d_out, int out_size)
{
    const float* x    = (const float*)d_in[0];
    const int*   ei   = (const int*)d_in[1];
    const int*   eli  = (const int*)d_in[2];
    const float* h1   = (const float*)d_in[3];
    const float* h2   = (const float*)d_in[4];
    const float* Wgcn = (const float*)d_in[5];
    const float* bgcn = (const float*)d_in[6];
    const float* Wx   = (const float*)d_in[7];
    const float* Th   = (const float*)d_in[8];
    const float* bgate= (const float*)d_in[9];
    const float* bconv= (const float*)d_in[10];
    const float* wc   = (const float*)d_in[11];
    const float* Wlin = (const float*)d_in[12];
    const float* blin = (const float*)d_in[13];

    float* out   = (float*)d_out;
    float* out_r = out;
    float* out_h = out + ELE;
    float* out_c = out + ELE + (size_t)NN * HH;

    const int T = 256;

    init_kernel<<<(NN + T - 1) / T, T>>>();
    deg_kernel<<<(EE + T - 1) / T, T>>>(ei + EE);
    scan_blocks<<<SCAN_B, 1024>>>();
    scan_bases<<<1, 64>>>();
    scan_fixup<<<SCAN_B, 1024>>>();
    fill_kernel<<<(EE + T - 1) / T, T>>>(ei, ei + EE);
    pack_B2<<<(KCAT * NG + T - 1) / T, T>>>(Wgcn, Wx, Th, bgate, bconv, bgcn);
    gather_kernel<<<(NN * 16 + T - 1) / T, T>>>(x, h1);
    {
        dim3 grid(NG / 128, MPAD / 128);
        gemm2_gates<<<grid, 512>>>(h2, wc, out_c);
    }
    lin_softmax<<<(NN + 7) / 8, 256>>>(Wlin, blin);
    decode_kernel<<<(ELE * 32 + T - 1) / T, T>>>(eli, eli + ELE, out_r);
    copy_h1<<<(NN * HH / 4 + T - 1) / T, T>>>(h1, out_h);
}

// round 8
// speedup vs baseline: 1.3768x; 1.0005x over previous
#include <cuda_runtime.h>
#include <math.h>
#include <stdint.h>

// Problem constants (fixed by the reference)
#define NN   50000      // nodes
#define FF   64         // node features
#define HH   128        // hidden
#define CLSN 64         // classes
#define EE   800000     // edges
#define ELE  200000     // label edges
#define MPAD 50048      // 391 * 128, padded M (no row guards on scratch)
#define KCAT 192        // FF + HH
#define NG   512        // 4*HH

#define SCAN_B 49       // ceil(NN / 1024)

// ---------------- scratch (device globals: allocation-free, zero-initialized) ----
__device__ float g_deg  [MPAD];
__device__ float g_dinv [MPAD];
__device__ int   g_off  [MPAD];                 // CSR row offsets (by dst)
__device__ int   g_cur  [MPAD];                 // fill cursors
__device__ int   g_bsum [64];                   // per-block totals
__device__ int   g_bbase[64];                   // exclusive block bases
__device__ int   g_esrc [EE];                   // CSR: src per slot
__device__ float g_abuf [(size_t)MPAD * KCAT];  // [Ax | hidden1], tf32-rounded
__device__ float g_B2   [KCAT * NG];            // [W_gcn@Wx ; Th], gate-interleaved, tf32
__device__ float g_bias2[NG];                   // b_gate + b_conv + b_gcn@Wx, interleaved
__device__ float g_hn   [(size_t)MPAD * HH];    // relu(H_new)
__device__ float g_z    [(size_t)MPAD * CLSN];  // softmax output

__device__ __forceinline__ float sigm(float x) { return 1.0f / (1.0f + expf(-x)); }

__device__ __forceinline__ float to_tf32(float x) {
    uint32_t o;
    asm("cvt.rna.tf32.f32 %0, %1;" : "=r"(o) : "f"(x));
    return __uint_as_float(o);
}

// ---------------- init: deg = 1 (self loop) -------------------------------------
__global__ void init_kernel() {
    int i = blockIdx.x * blockDim.x + threadIdx.x;
    if (i < NN) g_deg[i] = 1.0f;
}

__global__ void deg_kernel(const int* __restrict__ dst) {
    int e = blockIdx.x * blockDim.x + threadIdx.x;
    if (e < EE) atomicAdd(&g_deg[dst[e]], 1.0f);
}

// ---------------- parallel 3-pass exclusive scan (+ dinv fused) ------------------
__global__ void __launch_bounds__(1024)
scan_blocks() {
    __shared__ int wsum[32];
    int t = threadIdx.x, i = blockIdx.x * 1024 + t;
    int lane = t & 31, warp = t >> 5;
    float dg = (i < NN) ? g_deg[i] : 1.0f;
    if (i < NN) g_dinv[i] = rsqrtf(dg);          // fused dinv
    int cnt = (i < NN) ? ((int)dg - 1) : 0;

    int inc = cnt;
    #pragma unroll
    for (int o = 1; o < 32; o <<= 1) {
        int v = __shfl_up_sync(0xFFFFFFFFu, inc, o);
        if (lane >= o) inc += v;
    }
    if (lane == 31) wsum[warp] = inc;
    __syncthreads();
    if (warp == 0) {
        int w = wsum[lane];
        #pragma unroll
        for (int o = 1; o < 32; o <<= 1) {
            int v = __shfl_up_sync(0xFFFFFFFFu, w, o);
            if (lane >= o) w += v;
        }
        wsum[lane] = w;
        if (lane == 31) g_bsum[blockIdx.x] = w;
    }
    __syncthreads();
    int base = (warp > 0) ? wsum[warp - 1] : 0;
    if (i < NN) g_off[i] = base + inc - cnt;
}

__global__ void __launch_bounds__(64)
scan_bases() {
    __shared__ int s[64];
    int t = threadIdx.x;
    s[t] = (t < SCAN_B) ? g_bsum[t] : 0;
    __syncthreads();
    #pragma unroll
    for (int o = 1; o < 64; o <<= 1) {
        int v = (t >= o) ? s[t - o] : 0;
        __syncthreads();
        s[t] += v;
        __syncthreads();
    }
    if (t < SCAN_B) g_bbase[t] = s[t] - g_bsum[t];
}

__global__ void __launch_bounds__(1024)
scan_fixup() {
    int i = blockIdx.x * 1024 + threadIdx.x;
    if (i < NN) {
        int o = g_off[i] + g_bbase[blockIdx.x];
        g_off[i] = o;
        g_cur[i] = o;
    }
}

// ---------------- CSR fill ------------------------------------------------------
__global__ void fill_kernel(const int* __restrict__ src, const int* __restrict__ dst) {
    int e = blockIdx.x * blockDim.x + threadIdx.x;
    if (e >= EE) return;
    int slot = atomicAdd(&g_cur[dst[e]], 1);
    g_esrc[slot] = src[e];
}

// ---------------- gather on raw x: abuf = [ (Ax) | hidden1 ], tf32 ----------------
__global__ void __launch_bounds__(256)
gather_kernel(const float* __restrict__ x, const float* __restrict__ h1)
{
    int t = blockIdx.x * blockDim.x + threadIdx.x;
    int n = t >> 4, lane = t & 15;
    if (n >= NN) return;

    const float4* x4 = reinterpret_cast<const float4*>(x);
    int beg = g_off[n];
    int cnt = (int)g_deg[n] - 1;

    float4 acc = make_float4(0.f, 0.f, 0.f, 0.f);
    for (int i = beg; i < beg + cnt; i++) {
        int s = __ldg(&g_esrc[i]);
        float w = __ldg(&g_dinv[s]);
        float4 v = __ldg(&x4[(size_t)s * 16 + lane]);
        acc.x += w * v.x; acc.y += w * v.y; acc.z += w * v.z; acc.w += w * v.w;
    }
    float dn = g_dinv[n];
    float4 self = x4[(size_t)n * 16 + lane];
    float4 h;
    h.x = to_tf32(dn * acc.x + dn * dn * self.x);
    h.y = to_tf32(dn * acc.y + dn * dn * self.y);
    h.z = to_tf32(dn * acc.z + dn * dn * self.z);
    h.w = to_tf32(dn * acc.w + dn * dn * self.w);
    *reinterpret_cast<float4*>(&g_abuf[(size_t)n * KCAT + lane * 4]) = h;

    const float4* h14 = reinterpret_cast<const float4*>(h1);
    #pragma unroll
    for (int q = 0; q < 2; q++) {
        float4 v = __ldg(&h14[(size_t)n * 32 + lane * 2 + q]);
        v.x = to_tf32(v.x); v.y = to_tf32(v.y); v.z = to_tf32(v.z); v.w = to_tf32(v.w);
        *reinterpret_cast<float4*>(&g_abuf[(size_t)n * KCAT + FF + lane * 8 + q * 4]) = v;
    }
}

// ---------------- pack B2: rows 0..63 = W_gcn@Wx, rows 64..191 = Th --------------
// gate-interleaved columns (new col = 4j+g <=> old col = g*128+j), tf32-rounded
__global__ void pack_B2(const float* __restrict__ Wgcn, const float* __restrict__ Wx,
                        const float* __restrict__ Th,
                        const float* __restrict__ bgate, const float* __restrict__ bconv,
                        const float* __restrict__ bgcn)
{
    int i = blockIdx.x * blockDim.x + threadIdx.x;
    if (i >= KCAT * NG) return;
    int k = i / NG, col = i - k * NG;
    int j = col >> 2, g = col & 3;
    int old = g * HH + j;
    float v;
    if (k < FF) {
        float s = 0.0f;
        #pragma unroll 8
        for (int q = 0; q < FF; q++)
            s += Wgcn[k * FF + q] * Wx[(size_t)q * NG + old];
        v = s;
    } else {
        v = Th[(size_t)(k - FF) * NG + old];
    }
    g_B2[i] = to_tf32(v);
    if (i < NG) {
        float s = bgate[old] + bconv[old];
        #pragma unroll 8
        for (int q = 0; q < FF; q++)
            s += bgcn[q] * Wx[(size_t)q * NG + old];
        g_bias2[i] = s;
    }
}

// ---------------- tf32 MMA GEMM2 (128x128 tiles) + shuffle gate epilogue ---------
#define AS_STRIDE 36    // bank = (4*r + k) % 32 -> conflict-free A frag reads
#define BS_STRIDE 136   // 136 % 32 == 8 -> bank = (8*tg + gid) distinct

__device__ __forceinline__ void mma8(float* c, const uint32_t* a, const uint32_t* b) {
    asm volatile("mma.sync.aligned.m16n8k8.row.col.f32.tf32.tf32.f32 "
        "{%0,%1,%2,%3}, {%4,%5,%6,%7}, {%8,%9}, {%0,%1,%2,%3};"
        : "+f"(c[0]), "+f"(c[1]), "+f"(c[2]), "+f"(c[3])
        : "r"(a[0]), "r"(a[1]), "r"(a[2]), "r"(a[3]), "r"(b[0]), "r"(b[1]));
}

__global__ void __launch_bounds__(512)
gemm2_gates(const float* __restrict__ h2, const float* __restrict__ wc,
            float* __restrict__ outC)
{
    __shared__ __align__(16) float As[128 * AS_STRIDE];   // 18.4 KB
    __shared__ __align__(16) float Bs[32 * BS_STRIDE];    // 17.4 KB

    const int tid  = threadIdx.x;
    const int lane = tid & 31, warp = tid >> 5;
    const int wm = warp & 3, wn = warp >> 2;      // 4 M-warps x 4 N-warps
    const int gid = lane >> 2, tg = lane & 3;
    const int rowBase = blockIdx.y * 128;
    const int colBase = blockIdx.x * 128;

    // prefetch mapping: A 128x32 (1024 f4, 2/thread), B 32x128 (1024 f4, 2/thread)
    const int am = tid >> 3, ak4 = (tid & 7) << 2;
    const int bk = tid >> 5, bn4 = (tid & 31) << 2;
    const float* aptr = &g_abuf[(size_t)(rowBase + am) * KCAT + ak4];
    const float* bptr = &g_B2[(size_t)bk * NG + colBase + bn4];

    float acc[2][4][4];
    #pragma unroll
    for (int mt = 0; mt < 2; mt++)
        #pragma unroll
        for (int nt = 0; nt < 4; nt++)
            #pragma unroll
            for (int r = 0; r < 4; r++) acc[mt][nt][r] = 0.0f;

    float4 ra[2], rb[2];
    ra[0] = *reinterpret_cast<const float4*>(aptr);
    ra[1] = *reinterpret_cast<const float4*>(aptr + (size_t)64 * KCAT);
    rb[0] = *reinterpret_cast<const float4*>(bptr);
    rb[1] = *reinterpret_cast<const float4*>(bptr + (size_t)16 * NG);

    #pragma unroll
    for (int c = 0; c < 6; c++) {
        __syncthreads();
        *reinterpret_cast<float4*>(&As[am * AS_STRIDE + ak4]) = ra[0];
        *reinterpret_cast<float4*>(&As[(am + 64) * AS_STRIDE + ak4]) = ra[1];
        *reinterpret_cast<float4*>(&Bs[bk * BS_STRIDE + bn4]) = rb[0];
        *reinterpret_cast<float4*>(&Bs[(bk + 16) * BS_STRIDE + bn4]) = rb[1];
        __syncthreads();

        if (c < 5) {
            int kc = (c + 1) * 32;
            ra[0] = *reinterpret_cast<const float4*>(aptr + kc);
            ra[1] = *reinterpret_cast<const float4*>(aptr + (size_t)64 * KCAT + kc);
            rb[0] = *reinterpret_cast<const float4*>(bptr + (size_t)kc * NG);
            rb[1] = *reinterpret_cast<const float4*>(bptr + (size_t)(kc + 16) * NG);
        }

        #pragma unroll
        for (int ks = 0; ks < 32; ks += 8) {
            uint32_t a[2][4], b[4][2];
            #pragma unroll
            for (int mt = 0; mt < 2; mt++) {
                int r0 = wm * 32 + mt * 16 + gid;
                a[mt][0] = __float_as_uint(As[r0 * AS_STRIDE + ks + tg]);
                a[mt][1] = __float_as_uint(As[(r0 + 8) * AS_STRIDE + ks + tg]);
                a[mt][2] = __float_as_uint(As[r0 * AS_STRIDE + ks + tg + 4]);
                a[mt][3] = __float_as_uint(As[(r0 + 8) * AS_STRIDE + ks + tg + 4]);
            }
            #pragma unroll
            for (int nt = 0; nt < 4; nt++) {
                int c0 = wn * 32 + nt * 8 + gid;
                b[nt][0] = __float_as_uint(Bs[(ks + tg) * BS_STRIDE + c0]);
                b[nt][1] = __float_as_uint(Bs[(ks + tg + 4) * BS_STRIDE + c0]);
            }
            #pragma unroll
            for (int mt = 0; mt < 2; mt++)
                #pragma unroll
                for (int nt = 0; nt < 4; nt++)
                    mma8(acc[mt][nt], a[mt], b[nt]);
        }
    }

    // shuffle-based gate epilogue: lane pairs (lane^1) exchange gate halves.
    // fragment: c0,c1 = (row gid, cols 2tg, 2tg+1); c2,c3 = (row gid+8, same cols).
    // even tg holds (i,f) of hidden j, odd tg holds (c,o) of the same j.
    #pragma unroll
    for (int nt = 0; nt < 4; nt++) {
        int col = colBase + wn * 32 + nt * 8 + tg * 2;
        int j = col >> 2;
        float4 b4 = *reinterpret_cast<const float4*>(&g_bias2[j * 4]);
        float w0 = wc[j], w1 = wc[HH + j], w2 = wc[2 * HH + j];
        #pragma unroll
        for (int mt = 0; mt < 2; mt++) {
            float c0 = acc[mt][nt][0], c1 = acc[mt][nt][1];
            float c2 = acc[mt][nt][2], c3 = acc[mt][nt][3];
            float v0 = __shfl_xor_sync(0xFFFFFFFFu, c0, 1);
            float v1 = __shfl_xor_sync(0xFFFFFFFFu, c1, 1);
            float v2 = __shfl_xor_sync(0xFFFFFFFFu, c2, 1);
            float v3 = __shfl_xor_sync(0xFFFFFFFFu, c3, 1);
            int R = rowBase + wm * 32 + mt * 16;
            int row;
            float gi, gf, gc, go;
            if (!(tg & 1)) { row = R + gid;     gi = c0; gf = c1; gc = v0; go = v1; }
            else           { row = R + gid + 8; gi = v2; gf = v3; gc = c2; go = c3; }
            if (row < NN) {
                float cc = h2[(size_t)row * HH + j];
                float I  = sigm(gi + b4.x + w0 * cc);
                float Fg = sigm(gf + b4.y + w1 * cc);
                float Cn = Fg * cc + I * tanhf(gc + b4.z);
                float O  = sigm(go + b4.w + w2 * Cn);
                outC[(size_t)row * HH + j] = Cn;
                g_hn[(size_t)row * HH + j] = fmaxf(O * tanhf(Cn), 0.0f);
            }
        }
    }
}

// ---------------- Linear + softmax ----------------------------------------------
__global__ void __launch_bounds__(256)
lin_softmax(const float* __restrict__ Wl, const float* __restrict__ bl)
{
    __shared__ float sW[HH * CLSN];
    __shared__ float sb[CLSN];
    __shared__ float sh[8][HH];

    int tid = threadIdx.x;
    for (int i = tid * 4; i < HH * CLSN; i += 256 * 4)
        *reinterpret_cast<float4*>(&sW[i]) = *reinterpret_cast<const float4*>(&Wl[i]);
    if (tid < CLSN) sb[tid] = bl[tid];
    int warp = tid >> 5, lane = tid & 31;
    int n = blockIdx.x * 8 + warp;
    __syncthreads();

    if (n < NN) {
        for (int k = lane; k < HH; k += 32) sh[warp][k] = g_hn[(size_t)n * HH + k];
        __syncwarp();
        float a0 = sb[lane], a1 = sb[lane + 32];
        #pragma unroll 8
        for (int k = 0; k < HH; k++) {
            float hv = sh[warp][k];
            a0 += hv * sW[k * CLSN + lane];
            a1 += hv * sW[k * CLSN + lane + 32];
        }
        float m = fmaxf(a0, a1);
        #pragma unroll
        for (int o = 16; o; o >>= 1) m = fmaxf(m, __shfl_xor_sync(0xFFFFFFFFu, m, o));
        float e0 = expf(a0 - m), e1 = expf(a1 - m);
        float s = e0 + e1;
        #pragma unroll
        for (int o = 16; o; o >>= 1) s += __shfl_xor_sync(0xFFFFFFFFu, s, o);
        float inv = 1.0f / s;
        g_z[(size_t)n * CLSN + lane]      = e0 * inv;
        g_z[(size_t)n * CLSN + lane + 32] = e1 * inv;
    }
}

// ---------------- decode --------------------------------------------------------
__global__ void decode_kernel(const int* __restrict__ s, const int* __restrict__ d,
                              float* __restrict__ r)
{
    int w = (blockIdx.x * blockDim.x + threadIdx.x) >> 5;
    int lane = threadIdx.x & 31;
    if (w >= ELE) return;
    int a = __ldg(&s[w]);
    int b = __ldg(&d[w]);
    float acc = g_z[(size_t)a * CLSN + lane]      * g_z[(size_t)b * CLSN + lane]
              + g_z[(size_t)a * CLSN + lane + 32] * g_z[(size_t)b * CLSN + lane + 32];
    #pragma unroll
    for (int o = 16; o; o >>= 1) acc += __shfl_xor_sync(0xFFFFFFFFu, acc, o);
    if (lane == 0) r[w] = acc;
}

// ---------------- copy hidden1 passthrough --------------------------------------
__global__ void copy_h1(const float* __restrict__ h1, float* __restrict__ out) {
    int i = blockIdx.x * blockDim.x + threadIdx.x;
    if (i < NN * HH / 4)
        reinterpret_cast<float4*>(out)[i] = reinterpret_cast<const float4*>(h1)[i];
}

// ================================================================================
extern "C" void kernel_launch(void* const* d_in, const int* in_sizes, int n_in,
                              void* d_out, int out_size)
{
    const float* x    = (const float*)d_in[0];
    const int*   ei   = (const int*)d_in[1];
    const int*   eli  = (const int*)d_in[2];
    const float* h1   = (const float*)d_in[3];
    const float* h2   = (const float*)d_in[4];
    const float* Wgcn = (const float*)d_in[5];
    const float* bgcn = (const float*)d_in[6];
    const float* Wx   = (const float*)d_in[7];
    const float* Th   = (const float*)d_in[8];
    const float* bgate= (const float*)d_in[9];
    const float* bconv= (const float*)d_in[10];
    const float* wc   = (const float*)d_in[11];
    const float* Wlin = (const float*)d_in[12];
    const float* blin = (const float*)d_in[13];

    float* out   = (float*)d_out;
    float* out_r = out;
    float* out_h = out + ELE;
    float* out_c = out + ELE + (size_t)NN * HH;

    const int T = 256;

    init_kernel<<<(NN + T - 1) / T, T>>>();
    deg_kernel<<<(EE + T - 1) / T, T>>>(ei + EE);
    scan_blocks<<<SCAN_B, 1024>>>();
    scan_bases<<<1, 64>>>();
    scan_fixup<<<SCAN_B, 1024>>>();
    fill_kernel<<<(EE + T - 1) / T, T>>>(ei, ei + EE);
    pack_B2<<<(KCAT * NG + T - 1) / T, T>>>(Wgcn, Wx, Th, bgate, bconv, bgcn);
    gather_kernel<<<(NN * 16 + T - 1) / T, T>>>(x, h1);
    {
        dim3 grid(NG / 128, MPAD / 128);
        gemm2_gates<<<grid, 512>>>(h2, wc, out_c);
    }
    lin_softmax<<<(NN + 7) / 8, 256>>>(Wlin, blin);
    decode_kernel<<<(ELE * 32 + T - 1) / T, T>>>(eli, eli + ELE, out_r);
    copy_h1<<<(NN * HH / 4 + T - 1) / T, T>>>(h1, out_h);
}